// round 14
// baseline (speedup 1.0000x reference)
#include <cuda_runtime.h>
#include <cuda_bf16.h>
#include <math.h>
#include <stdint.h>

#define TT  8192
#define HH  1024
#define EE  8
#define CAP 1280
#define IRR 4096
#define ISS 8192

#define A_LO 10240
#define B_HI 20480
#define B_LO 29184
#define SM_BUF 37888
#define SM_TOT3 (3 * SM_BUF)
#define FA_LO 10240
#define FBG_HI 20480
#define FBG_LO 25088
#define FBU_HI 29696
#define FBU_LO 34304
#define F_BUF 38912
#define F_TOT (2 * F_BUF)

typedef __nv_bfloat16 bf;

__device__ bf g_xh[(size_t)TT * HH],  g_xl[(size_t)TT * HH];
__device__ bf g_sgh[(size_t)HH * ISS], g_sgl[(size_t)HH * ISS];
__device__ bf g_suh[(size_t)HH * ISS], g_sul[(size_t)HH * ISS];
__device__ bf g_sdh[(size_t)ISS * HH], g_sdl[(size_t)ISS * HH];
__device__ bf g_rgh[(size_t)EE * HH * IRR], g_rgl[(size_t)EE * HH * IRR];
__device__ bf g_ruh[(size_t)EE * HH * IRR], g_rul[(size_t)EE * HH * IRR];
__device__ bf g_rdh[(size_t)EE * IRR * HH], g_rdl[(size_t)EE * IRR * HH];
__device__ bf g_acth[(size_t)TT * ISS], g_actl[(size_t)TT * ISS];
__device__ int   g_tki[TT * 2];
__device__ float g_tkw[TT * 2];
__device__ int   g_disp[EE * CAP];
__device__ float g_gw[EE * CAP];

__device__ __forceinline__ uint32_t smem_u32(const void* p) {
    uint32_t a;
    asm("{ .reg .u64 t; cvta.to.shared.u64 t, %1; cvt.u32.u64 %0, t; }" : "=r"(a) : "l"(p));
    return a;
}
__device__ __forceinline__ void ldsm4(uint32_t* r, uint32_t addr) {
    asm volatile("ldmatrix.sync.aligned.m8n8.x4.shared.b16 {%0,%1,%2,%3}, [%4];"
        : "=r"(r[0]), "=r"(r[1]), "=r"(r[2]), "=r"(r[3]) : "r"(addr));
}
__device__ __forceinline__ void ldsm4t(uint32_t* r, uint32_t addr) {
    asm volatile("ldmatrix.sync.aligned.m8n8.x4.trans.shared.b16 {%0,%1,%2,%3}, [%4];"
        : "=r"(r[0]), "=r"(r[1]), "=r"(r[2]), "=r"(r[3]) : "r"(addr));
}
__device__ __forceinline__ void mma16816(float* d, const uint32_t* a, uint32_t b0, uint32_t b1) {
    asm volatile("mma.sync.aligned.m16n8k16.row.col.f32.bf16.bf16.f32 "
        "{%0,%1,%2,%3}, {%4,%5,%6,%7}, {%8,%9}, {%0,%1,%2,%3};"
        : "+f"(d[0]), "+f"(d[1]), "+f"(d[2]), "+f"(d[3])
        : "r"(a[0]), "r"(a[1]), "r"(a[2]), "r"(a[3]), "r"(b0), "r"(b1));
}
#define CPA16(dst, src) asm volatile("cp.async.cg.shared.global [%0], [%1], 16;" :: "r"(dst), "l"(src) : "memory")
#define CPA_COMMIT()    asm volatile("cp.async.commit_group;" ::: "memory")
#define CPA_WAIT0()     asm volatile("cp.async.wait_group 0;" ::: "memory")
#define CPA_WAIT1()     asm volatile("cp.async.wait_group 1;" ::: "memory")

__global__ void cvt_split(const float* __restrict__ in, bf* __restrict__ hi,
                          bf* __restrict__ lo, size_t n)
{
    size_t stride = (size_t)gridDim.x * blockDim.x * 8;
    for (size_t i = ((size_t)blockIdx.x * blockDim.x + threadIdx.x) * 8; i < n; i += stride) {
        float4 v0 = *(const float4*)(in + i);
        float4 v1 = *(const float4*)(in + i + 4);
        __nv_bfloat162 h0 = __floats2bfloat162_rn(v0.x, v0.y);
        __nv_bfloat162 h1 = __floats2bfloat162_rn(v0.z, v0.w);
        __nv_bfloat162 h2 = __floats2bfloat162_rn(v1.x, v1.y);
        __nv_bfloat162 h3 = __floats2bfloat162_rn(v1.z, v1.w);
        __nv_bfloat162 l0 = __floats2bfloat162_rn(v0.x - __bfloat162float(h0.x),
                                                  v0.y - __bfloat162float(h0.y));
        __nv_bfloat162 l1 = __floats2bfloat162_rn(v0.z - __bfloat162float(h1.x),
                                                  v0.w - __bfloat162float(h1.y));
        __nv_bfloat162 l2 = __floats2bfloat162_rn(v1.x - __bfloat162float(h2.x),
                                                  v1.y - __bfloat162float(h2.y));
        __nv_bfloat162 l3 = __floats2bfloat162_rn(v1.z - __bfloat162float(h3.x),
                                                  v1.w - __bfloat162float(h3.y));
        *(__nv_bfloat162*)(hi + i) = h0;     *(__nv_bfloat162*)(hi + i + 2) = h1;
        *(__nv_bfloat162*)(hi + i + 4) = h2; *(__nv_bfloat162*)(hi + i + 6) = h3;
        *(__nv_bfloat162*)(lo + i) = l0;     *(__nv_bfloat162*)(lo + i + 2) = l1;
        *(__nv_bfloat162*)(lo + i + 4) = l2; *(__nv_bfloat162*)(lo + i + 6) = l3;
    }
}

__global__ void router_kernel(const float* __restrict__ x, const float* __restrict__ rw)
{
    int t = blockIdx.x;
    const float* xr = x + (size_t)t * HH;
    float ss = 0.f, dot[EE];
#pragma unroll
    for (int e = 0; e < EE; e++) dot[e] = 0.f;
    for (int i = threadIdx.x; i < HH; i += 256) {
        float v = xr[i];
        ss += v * v;
#pragma unroll
        for (int e = 0; e < EE; e++) dot[e] += v * rw[e * HH + i];
    }
#pragma unroll
    for (int off = 16; off > 0; off >>= 1) {
        ss += __shfl_down_sync(0xffffffffu, ss, off);
#pragma unroll
        for (int e = 0; e < EE; e++) dot[e] += __shfl_down_sync(0xffffffffu, dot[e], off);
    }
    __shared__ float red[8][9];
    int warp = threadIdx.x >> 5, lane = threadIdx.x & 31;
    if (lane == 0) {
        red[warp][0] = ss;
#pragma unroll
        for (int e = 0; e < EE; e++) red[warp][1 + e] = dot[e];
    }
    __syncthreads();
    if (threadIdx.x == 0) {
        float s = 0.f, d[EE];
#pragma unroll
        for (int e = 0; e < EE; e++) d[e] = 0.f;
        for (int w2 = 0; w2 < 8; w2++) {
            s += red[w2][0];
#pragma unroll
            for (int e = 0; e < EE; e++) d[e] += red[w2][1 + e];
        }
        float r = rsqrtf(s / (float)HH + 1.1920929e-7f);
        float lg[EE];
#pragma unroll
        for (int e = 0; e < EE; e++) lg[e] = d[e] * r;
        int i1 = 0;
        for (int e = 1; e < EE; e++) if (lg[e] > lg[i1]) i1 = e;
        int i2 = -1;
        for (int e = 0; e < EE; e++) {
            if (e == i1) continue;
            if (i2 < 0 || lg[e] > lg[i2]) i2 = e;
        }
        float e2 = expf(lg[i2] - lg[i1]);
        float inv = 1.f / (1.f + e2);
        g_tki[t * 2] = i1; g_tki[t * 2 + 1] = i2;
        g_tkw[t * 2] = inv; g_tkw[t * 2 + 1] = e2 * inv;
    }
}

__global__ void dispatch_kernel()
{
    int e = blockIdx.x, tid = threadIdx.x;
    int warp = tid >> 5, lane = tid & 31;
    __shared__ int wsum[8];
    __shared__ int base_s;
    for (int s = tid; s < CAP; s += 256) { g_disp[e*CAP+s] = 0; g_gw[e*CAP+s] = 0.f; }
    if (tid == 0) base_s = 0;
    __syncthreads();
    for (int c0 = 0; c0 < TT; c0 += 256) {
        int t = c0 + tid;
        int i0 = g_tki[t*2], i1 = g_tki[t*2+1];
        float wt = (i0 == e) ? g_tkw[t*2] : ((i1 == e) ? g_tkw[t*2+1] : 0.f);
        int sel = (i0 == e) || (i1 == e);
        unsigned m = __ballot_sync(0xffffffffu, sel);
        int wpre = __popc(m & ((1u << lane) - 1u));
        if (lane == 0) wsum[warp] = __popc(m);
        __syncthreads();
        int woff = 0;
        for (int w = 0; w < warp; w++) woff += wsum[w];
        int slot = base_s + woff + wpre;
        if (sel && slot < CAP) { g_disp[e*CAP+slot] = t; g_gw[e*CAP+slot] = wt; }
        __syncthreads();
        if (tid == 0) {
            int tot = 0;
            for (int w = 0; w < 8; w++) tot += wsum[w];
            base_s += tot;
        }
        __syncthreads();
    }
}

// Fused gate+up (2-stage double buffer, unchanged layout from R13).
template <bool GATHER>
__global__ void __launch_bounds__(256, 2) fused_gateup_k(
    const bf* __restrict__ Ah, const bf* __restrict__ Al,
    const bf* __restrict__ Bgh, const bf* __restrict__ Bgl,
    const bf* __restrict__ Buh, const bf* __restrict__ Bul,
    bf* __restrict__ acth, bf* __restrict__ actl,
    int Kd, int N, size_t sB, size_t sC,
    const int* __restrict__ disp)
{
    extern __shared__ char smem[];
    uint32_t sbu = smem_u32(smem);
    int tid = threadIdx.x, wid = tid >> 5, lane = tid & 31;
    int z = blockIdx.z;
    int bm = blockIdx.y * 128, bn = blockIdx.x * 64;
    int wm = wid & 1, wn = wid >> 1;

    int arw = tid >> 1, ahalf = tid & 1;
    int bkr = tid >> 3, bseg = tid & 7;
    size_t arow;
    if (GATHER) arow = (size_t)disp[z * CAP + bm + arw];
    else        arow = (size_t)(bm + arw);
    const bf* Ahp = Ah + arow * Kd + ahalf * 16;
    const bf* Alp = Al + arow * Kd + ahalf * 16;
    size_t boff = (size_t)z * sB + (size_t)bkr * N + bn + bseg * 8;
    const bf* Bghp = Bgh + boff;
    const bf* Bglp = Bgl + boff;
    const bf* Buhp = Buh + boff;
    const bf* Bulp = Bul + boff;
    uint32_t a_st = (uint32_t)arw * 80u + (uint32_t)ahalf * 32u;
    uint32_t b_st = (uint32_t)bkr * 144u + (uint32_t)bseg * 16u;

    int li = lane & 15, kh = (lane >> 4) << 3;
    uint32_t a_ld = sbu + (uint32_t)(wm * 64 + li) * 80u + (uint32_t)kh * 2u;
    uint32_t b_ld = sbu + (uint32_t)li * 144u + (uint32_t)(wn * 16 + kh) * 2u;

    float accg[4][2][4], accu[4][2][4];
#pragma unroll
    for (int i = 0; i < 4; i++)
#pragma unroll
        for (int j = 0; j < 2; j++)
#pragma unroll
            for (int c = 0; c < 4; c++) { accg[i][j][c] = 0.f; accu[i][j][c] = 0.f; }

    const int NIT = Kd / 32;
    {
        uint32_t sa = sbu + a_st;
        CPA16(sa, Ahp);        CPA16(sa + 16, Ahp + 8);
        CPA16(sa + FA_LO, Alp); CPA16(sa + FA_LO + 16, Alp + 8);
        uint32_t sbb = sbu + b_st;
        CPA16(sbb + FBG_HI, Bghp);
        CPA16(sbb + FBG_LO, Bglp);
        CPA16(sbb + FBU_HI, Buhp);
        CPA16(sbb + FBU_LO, Bulp);
        CPA_COMMIT();
        CPA_WAIT0();
    }
    __syncthreads();

    for (int it = 0; it < NIT; it++) {
        if (it + 1 < NIT) {
            int k0 = (it + 1) * 32;
            uint32_t so = (uint32_t)((it + 1) & 1) * F_BUF;
            uint32_t sa = sbu + so + a_st;
            const bf* ah = Ahp + k0;
            const bf* al = Alp + k0;
            CPA16(sa, ah);         CPA16(sa + 16, ah + 8);
            CPA16(sa + FA_LO, al); CPA16(sa + FA_LO + 16, al + 8);
            uint32_t sbb = sbu + so + b_st;
            size_t go = (size_t)k0 * N;
            CPA16(sbb + FBG_HI, Bghp + go);
            CPA16(sbb + FBG_LO, Bglp + go);
            CPA16(sbb + FBU_HI, Buhp + go);
            CPA16(sbb + FBU_LO, Bulp + go);
            CPA_COMMIT();
        }
        uint32_t bo = (uint32_t)(it & 1) * F_BUF;
#pragma unroll
        for (int k0 = 0; k0 < 32; k0 += 16) {
            uint32_t ah[4][4], al[4][4];
#pragma unroll
            for (int mt = 0; mt < 4; mt++) {
                uint32_t ad = a_ld + bo + (uint32_t)mt * 1280u + (uint32_t)k0 * 2u;
                ldsm4(ah[mt], ad);
                ldsm4(al[mt], ad + FA_LO);
            }
            uint32_t brow = b_ld + bo + (uint32_t)k0 * 144u;
            {
                uint32_t bh[4], bl[4];
                ldsm4t(bh, brow + FBG_HI);
                ldsm4t(bl, brow + FBG_LO);
#pragma unroll
                for (int mt = 0; mt < 4; mt++)
#pragma unroll
                    for (int nt = 0; nt < 2; nt++) {
                        int r = nt * 2;
                        mma16816(accg[mt][nt], ah[mt], bh[r], bh[r + 1]);
                        mma16816(accg[mt][nt], ah[mt], bl[r], bl[r + 1]);
                        mma16816(accg[mt][nt], al[mt], bh[r], bh[r + 1]);
                    }
            }
            {
                uint32_t bh[4], bl[4];
                ldsm4t(bh, brow + FBU_HI);
                ldsm4t(bl, brow + FBU_LO);
#pragma unroll
                for (int mt = 0; mt < 4; mt++)
#pragma unroll
                    for (int nt = 0; nt < 2; nt++) {
                        int r = nt * 2;
                        mma16816(accu[mt][nt], ah[mt], bh[r], bh[r + 1]);
                        mma16816(accu[mt][nt], ah[mt], bl[r], bl[r + 1]);
                        mma16816(accu[mt][nt], al[mt], bh[r], bh[r + 1]);
                    }
            }
        }
        if (it + 1 < NIT) {
            CPA_WAIT0();
            __syncthreads();
        }
    }

    int g = lane >> 2, tg = lane & 3;
#pragma unroll
    for (int mt = 0; mt < 4; mt++) {
#pragma unroll
        for (int nt = 0; nt < 2; nt++) {
            int row0 = bm + wm * 64 + mt * 16 + g;
            int col = bn + wn * 16 + nt * 8 + tg * 2;
            float* dg = accg[mt][nt];
            float* du = accu[mt][nt];
            size_t o0 = (size_t)z * sC + (size_t)row0 * N + col;
            size_t o1 = o0 + (size_t)8 * N;
            float a0 = dg[0] / (1.f + expf(-dg[0])) * du[0];
            float a1 = dg[1] / (1.f + expf(-dg[1])) * du[1];
            float a2 = dg[2] / (1.f + expf(-dg[2])) * du[2];
            float a3 = dg[3] / (1.f + expf(-dg[3])) * du[3];
            __nv_bfloat162 h0 = __floats2bfloat162_rn(a0, a1);
            __nv_bfloat162 h1 = __floats2bfloat162_rn(a2, a3);
            __nv_bfloat162 l0 = __floats2bfloat162_rn(a0 - __bfloat162float(h0.x),
                                                      a1 - __bfloat162float(h0.y));
            __nv_bfloat162 l1 = __floats2bfloat162_rn(a2 - __bfloat162float(h1.x),
                                                      a3 - __bfloat162float(h1.y));
            *(__nv_bfloat162*)(acth + o0) = h0;
            *(__nv_bfloat162*)(acth + o1) = h1;
            *(__nv_bfloat162*)(actl + o0) = l0;
            *(__nv_bfloat162*)(actl + o1) = l1;
        }
    }
}

// Down-proj GEMM, 3-stage cp.async pipeline.
template <int EPI>
__global__ void __launch_bounds__(256, 2) hgemm_k(
    const bf* __restrict__ Ah, const bf* __restrict__ Al,
    const bf* __restrict__ Bh, const bf* __restrict__ Bl,
    float* __restrict__ outC,
    int Kd, int N, size_t sA, size_t sB,
    const int* __restrict__ disp, const float* __restrict__ wv)
{
    extern __shared__ char smem[];
    uint32_t sbu = smem_u32(smem);
    int tid = threadIdx.x, wid = tid >> 5, lane = tid & 31;
    int z = blockIdx.z;
    int bm = blockIdx.y * 128, bn = blockIdx.x * 128;
    int wm = wid & 1, wn = wid >> 1;

    int arw = tid >> 1, ahalf = tid & 1;
    int bkr = tid >> 3, bseg = tid & 7;
    const bf* Ahp = Ah + (size_t)z * sA + (size_t)(bm + arw) * Kd + ahalf * 16;
    const bf* Alp = Al + (size_t)z * sA + (size_t)(bm + arw) * Kd + ahalf * 16;
    const bf* Bhp = Bh + (size_t)z * sB + (size_t)bkr * N + bn + bseg * 16;
    const bf* Blp = Bl + (size_t)z * sB + (size_t)bkr * N + bn + bseg * 16;
    uint32_t a_st = (uint32_t)arw * 80u + (uint32_t)ahalf * 32u;
    uint32_t b_st = B_HI + (uint32_t)bkr * 272u + (uint32_t)bseg * 32u;

    int li = lane & 15, kh = (lane >> 4) << 3;
    uint32_t a_ld = sbu + (uint32_t)(wm * 64 + li) * 80u + (uint32_t)kh * 2u;
    uint32_t b_ld = sbu + B_HI + (uint32_t)li * 272u + (uint32_t)(wn * 32 + kh) * 2u;

    float acc[4][4][4];
#pragma unroll
    for (int i = 0; i < 4; i++)
#pragma unroll
        for (int j = 0; j < 4; j++)
#pragma unroll
            for (int c = 0; c < 4; c++) acc[i][j][c] = 0.f;

    const int NIT = Kd / 32;
    // prologue: issue chunks 0 and 1
    {
        uint32_t sa = sbu + a_st, sbb = sbu + b_st;
        CPA16(sa, Ahp);            CPA16(sa + 16, Ahp + 8);
        CPA16(sa + A_LO, Alp);     CPA16(sa + A_LO + 16, Alp + 8);
        CPA16(sbb, Bhp);           CPA16(sbb + 16, Bhp + 8);
        CPA16(sbb + (B_LO - B_HI), Blp); CPA16(sbb + (B_LO - B_HI) + 16, Blp + 8);
        CPA_COMMIT();
        if (NIT > 1) {
            uint32_t sa1 = sbu + SM_BUF + a_st, sb1 = sbu + SM_BUF + b_st;
            const bf* ah = Ahp + 32;
            const bf* al = Alp + 32;
            const bf* bh = Bhp + (size_t)32 * N;
            const bf* bl = Blp + (size_t)32 * N;
            CPA16(sa1, ah);            CPA16(sa1 + 16, ah + 8);
            CPA16(sa1 + A_LO, al);     CPA16(sa1 + A_LO + 16, al + 8);
            CPA16(sb1, bh);            CPA16(sb1 + 16, bh + 8);
            CPA16(sb1 + (B_LO - B_HI), bl); CPA16(sb1 + (B_LO - B_HI) + 16, bl + 8);
            CPA_COMMIT();
            CPA_WAIT1();
        } else {
            CPA_WAIT0();
        }
    }
    __syncthreads();

    int buf = 0, nbuf = (NIT > 1) ? 2 : 1;
    for (int it = 0; it < NIT; it++) {
        if (it + 2 < NIT) {
            int k0 = (it + 2) * 32;
            uint32_t so = (uint32_t)nbuf * SM_BUF;
            nbuf = (nbuf == 2) ? 0 : nbuf + 1;
            uint32_t sa = sbu + so + a_st, sbb = sbu + so + b_st;
            const bf* ah = Ahp + k0;
            const bf* al = Alp + k0;
            const bf* bh = Bhp + (size_t)k0 * N;
            const bf* bl = Blp + (size_t)k0 * N;
            CPA16(sa, ah);            CPA16(sa + 16, ah + 8);
            CPA16(sa + A_LO, al);     CPA16(sa + A_LO + 16, al + 8);
            CPA16(sbb, bh);           CPA16(sbb + 16, bh + 8);
            CPA16(sbb + (B_LO - B_HI), bl); CPA16(sbb + (B_LO - B_HI) + 16, bl + 8);
            CPA_COMMIT();
        }
        uint32_t bo = (uint32_t)buf * SM_BUF;
        buf = (buf == 2) ? 0 : buf + 1;
#pragma unroll
        for (int k0 = 0; k0 < 32; k0 += 16) {
            uint32_t ah[4][4], al[4][4];
#pragma unroll
            for (int mt = 0; mt < 4; mt++) {
                uint32_t ad = a_ld + bo + (uint32_t)mt * 1280u + (uint32_t)k0 * 2u;
                ldsm4(ah[mt], ad);
                ldsm4(al[mt], ad + A_LO);
            }
#pragma unroll
            for (int np = 0; np < 2; np++) {
                uint32_t bh[4], bl[4];
                uint32_t bd = b_ld + bo + (uint32_t)k0 * 272u + (uint32_t)np * 32u;
                ldsm4t(bh, bd);
                ldsm4t(bl, bd + (B_LO - B_HI));
#pragma unroll
                for (int mt = 0; mt < 4; mt++)
#pragma unroll
                    for (int half = 0; half < 2; half++) {
                        int nt = np * 2 + half;
                        int r = half * 2;
                        mma16816(acc[mt][nt], ah[mt], bh[r], bh[r + 1]);
                        mma16816(acc[mt][nt], ah[mt], bl[r], bl[r + 1]);
                        mma16816(acc[mt][nt], al[mt], bh[r], bh[r + 1]);
                    }
            }
        }
        if (it + 1 < NIT) {
            if (it + 2 < NIT) { CPA_WAIT1(); } else { CPA_WAIT0(); }
            __syncthreads();
        }
    }

    int g = lane >> 2, tg = lane & 3;
#pragma unroll
    for (int mt = 0; mt < 4; mt++) {
#pragma unroll
        for (int nt = 0; nt < 4; nt++) {
            int row0 = bm + wm * 64 + mt * 16 + g;
            int col = bn + wn * 32 + nt * 8 + tg * 2;
            float* d = acc[mt][nt];
            if (EPI == 0) {
                float* p0 = outC + (size_t)row0 * N + col;
                float* p1 = p0 + (size_t)8 * N;
                *(float2*)p0 = make_float2(d[0], d[1]);
                *(float2*)p1 = make_float2(d[2], d[3]);
            } else {
                int s0 = z * CAP + row0, s1 = s0 + 8;
                int t0 = disp[s0], t1 = disp[s1];
                float w0 = wv[s0], w1 = wv[s1];
                float* p0 = outC + (size_t)t0 * HH + col;
                float* p1 = outC + (size_t)t1 * HH + col;
                atomicAdd(p0 + 0, w0 * d[0]);
                atomicAdd(p0 + 1, w0 * d[1]);
                atomicAdd(p1 + 0, w1 * d[2]);
                atomicAdd(p1 + 1, w1 * d[3]);
            }
        }
    }
}

extern "C" void kernel_launch(void* const* d_in, const int* in_sizes, int n_in,
                              void* d_out, int out_size)
{
    const float* x  = (const float*)d_in[0];
    const float* rw = (const float*)d_in[1];
    const float* rg = (const float*)d_in[2];
    const float* ru = (const float*)d_in[3];
    const float* rd = (const float*)d_in[4];
    const float* sg = (const float*)d_in[5];
    const float* su = (const float*)d_in[6];
    const float* sd = (const float*)d_in[7];
    float* out = (float*)d_out;

    bf *xh, *xl, *sgh, *sgl, *suh, *sul, *sdh, *sdl, *rgh, *rgl, *ruh, *rul, *rdh, *rdl;
    bf *acth, *actl;
    float *gw;
    int *disp;
    cudaGetSymbolAddress((void**)&xh, g_xh);   cudaGetSymbolAddress((void**)&xl, g_xl);
    cudaGetSymbolAddress((void**)&sgh, g_sgh); cudaGetSymbolAddress((void**)&sgl, g_sgl);
    cudaGetSymbolAddress((void**)&suh, g_suh); cudaGetSymbolAddress((void**)&sul, g_sul);
    cudaGetSymbolAddress((void**)&sdh, g_sdh); cudaGetSymbolAddress((void**)&sdl, g_sdl);
    cudaGetSymbolAddress((void**)&rgh, g_rgh); cudaGetSymbolAddress((void**)&rgl, g_rgl);
    cudaGetSymbolAddress((void**)&ruh, g_ruh); cudaGetSymbolAddress((void**)&rul, g_rul);
    cudaGetSymbolAddress((void**)&rdh, g_rdh); cudaGetSymbolAddress((void**)&rdl, g_rdl);
    cudaGetSymbolAddress((void**)&acth, g_acth); cudaGetSymbolAddress((void**)&actl, g_actl);
    cudaGetSymbolAddress((void**)&gw, g_gw);
    cudaGetSymbolAddress((void**)&disp, g_disp);

    cudaFuncSetAttribute(fused_gateup_k<false>, cudaFuncAttributeMaxDynamicSharedMemorySize, F_TOT);
    cudaFuncSetAttribute(fused_gateup_k<true>,  cudaFuncAttributeMaxDynamicSharedMemorySize, F_TOT);
    cudaFuncSetAttribute(hgemm_k<0>, cudaFuncAttributeMaxDynamicSharedMemorySize, SM_TOT3);
    cudaFuncSetAttribute(hgemm_k<2>, cudaFuncAttributeMaxDynamicSharedMemorySize, SM_TOT3);

    cvt_split<<<2368, 256>>>(x,  xh,  xl,  (size_t)TT * HH);
    cvt_split<<<2368, 256>>>(sg, sgh, sgl, (size_t)HH * ISS);
    cvt_split<<<2368, 256>>>(su, suh, sul, (size_t)HH * ISS);
    cvt_split<<<2368, 256>>>(sd, sdh, sdl, (size_t)ISS * HH);
    cvt_split<<<2368, 256>>>(rg, rgh, rgl, (size_t)EE * HH * IRR);
    cvt_split<<<2368, 256>>>(ru, ruh, rul, (size_t)EE * HH * IRR);
    cvt_split<<<2368, 256>>>(rd, rdh, rdl, (size_t)EE * IRR * HH);

    router_kernel<<<TT, 256>>>(x, rw);
    dispatch_kernel<<<EE, 256>>>();

    fused_gateup_k<false><<<dim3(ISS / 64, TT / 128, 1), 256, F_TOT>>>(
        xh, xl, sgh, sgl, suh, sul, acth, actl, HH, ISS, 0, 0, (const int*)0);
    hgemm_k<0><<<dim3(HH / 128, TT / 128, 1), 256, SM_TOT3>>>(
        acth, actl, sdh, sdl, out, ISS, HH, 0, 0, (const int*)0, (const float*)0);

    fused_gateup_k<true><<<dim3(IRR / 64, CAP / 128, EE), 256, F_TOT>>>(
        xh, xl, rgh, rgl, ruh, rul, acth, actl, HH, IRR,
        (size_t)HH * IRR, (size_t)CAP * IRR, disp);
    hgemm_k<2><<<dim3(HH / 128, CAP / 128, EE), 256, SM_TOT3>>>(
        acth, actl, rdh, rdl, out, IRR, HH,
        (size_t)CAP * IRR, (size_t)IRR * HH, disp, gw);
}

// round 15
// speedup vs baseline: 1.0044x; 1.0044x over previous
#include <cuda_runtime.h>
#include <cuda_bf16.h>
#include <math.h>
#include <stdint.h>

#define TT  8192
#define HH  1024
#define EE  8
#define CAP 1280
#define IRR 4096
#define ISS 8192

#define A_LO 10240
#define B_HI 20480
#define B_LO 29184
#define SM_BUF 37888
#define SM_TOT (2 * SM_BUF)
#define FA_LO 10240
#define FBG_HI 20480
#define FBG_LO 25088
#define FBU_HI 29696
#define FBU_LO 34304
#define F_BUF 38912
#define F_TOT (2 * F_BUF)

typedef __nv_bfloat16 bf;

__device__ bf g_xh[(size_t)TT * HH],  g_xl[(size_t)TT * HH];
__device__ bf g_sgh[(size_t)HH * ISS], g_sgl[(size_t)HH * ISS];
__device__ bf g_suh[(size_t)HH * ISS], g_sul[(size_t)HH * ISS];
__device__ bf g_sdh[(size_t)ISS * HH], g_sdl[(size_t)ISS * HH];
__device__ bf g_rgh[(size_t)EE * HH * IRR], g_rgl[(size_t)EE * HH * IRR];
__device__ bf g_ruh[(size_t)EE * HH * IRR], g_rul[(size_t)EE * HH * IRR];
__device__ bf g_rdh[(size_t)EE * IRR * HH], g_rdl[(size_t)EE * IRR * HH];
__device__ bf g_acth[(size_t)TT * ISS], g_actl[(size_t)TT * ISS];
__device__ int   g_tki[TT * 2];
__device__ float g_tkw[TT * 2];
__device__ int   g_disp[EE * CAP];
__device__ float g_gw[EE * CAP];

__device__ __forceinline__ uint32_t smem_u32(const void* p) {
    uint32_t a;
    asm("{ .reg .u64 t; cvta.to.shared.u64 t, %1; cvt.u32.u64 %0, t; }" : "=r"(a) : "l"(p));
    return a;
}
__device__ __forceinline__ void ldsm4(uint32_t* r, uint32_t addr) {
    asm volatile("ldmatrix.sync.aligned.m8n8.x4.shared.b16 {%0,%1,%2,%3}, [%4];"
        : "=r"(r[0]), "=r"(r[1]), "=r"(r[2]), "=r"(r[3]) : "r"(addr));
}
__device__ __forceinline__ void ldsm4t(uint32_t* r, uint32_t addr) {
    asm volatile("ldmatrix.sync.aligned.m8n8.x4.trans.shared.b16 {%0,%1,%2,%3}, [%4];"
        : "=r"(r[0]), "=r"(r[1]), "=r"(r[2]), "=r"(r[3]) : "r"(addr));
}
__device__ __forceinline__ void mma16816(float* d, const uint32_t* a, uint32_t b0, uint32_t b1) {
    asm volatile("mma.sync.aligned.m16n8k16.row.col.f32.bf16.bf16.f32 "
        "{%0,%1,%2,%3}, {%4,%5,%6,%7}, {%8,%9}, {%0,%1,%2,%3};"
        : "+f"(d[0]), "+f"(d[1]), "+f"(d[2]), "+f"(d[3])
        : "r"(a[0]), "r"(a[1]), "r"(a[2]), "r"(a[3]), "r"(b0), "r"(b1));
}
#define CPA16(dst, src) asm volatile("cp.async.cg.shared.global [%0], [%1], 16;" :: "r"(dst), "l"(src) : "memory")
#define CPA_COMMIT()    asm volatile("cp.async.commit_group;" ::: "memory")
#define CPA_WAIT0()     asm volatile("cp.async.wait_group 0;" ::: "memory")

__global__ void cvt_split(const float* __restrict__ in, bf* __restrict__ hi,
                          bf* __restrict__ lo, size_t n)
{
    for (size_t i = ((size_t)blockIdx.x * blockDim.x + threadIdx.x) * 4; i < n;
         i += (size_t)gridDim.x * blockDim.x * 4) {
        float4 v = *(const float4*)(in + i);
        __nv_bfloat162 h0 = __floats2bfloat162_rn(v.x, v.y);
        __nv_bfloat162 h1 = __floats2bfloat162_rn(v.z, v.w);
        __nv_bfloat162 l0 = __floats2bfloat162_rn(v.x - __bfloat162float(h0.x),
                                                  v.y - __bfloat162float(h0.y));
        __nv_bfloat162 l1 = __floats2bfloat162_rn(v.z - __bfloat162float(h1.x),
                                                  v.w - __bfloat162float(h1.y));
        *(__nv_bfloat162*)(hi + i) = h0;
        *(__nv_bfloat162*)(hi + i + 2) = h1;
        *(__nv_bfloat162*)(lo + i) = l0;
        *(__nv_bfloat162*)(lo + i + 2) = l1;
    }
}

__global__ void router_kernel(const float* __restrict__ x, const float* __restrict__ rw)
{
    int t = blockIdx.x;
    const float* xr = x + (size_t)t * HH;
    float ss = 0.f, dot[EE];
#pragma unroll
    for (int e = 0; e < EE; e++) dot[e] = 0.f;
    for (int i = threadIdx.x; i < HH; i += 256) {
        float v = xr[i];
        ss += v * v;
#pragma unroll
        for (int e = 0; e < EE; e++) dot[e] += v * rw[e * HH + i];
    }
#pragma unroll
    for (int off = 16; off > 0; off >>= 1) {
        ss += __shfl_down_sync(0xffffffffu, ss, off);
#pragma unroll
        for (int e = 0; e < EE; e++) dot[e] += __shfl_down_sync(0xffffffffu, dot[e], off);
    }
    __shared__ float red[8][9];
    int warp = threadIdx.x >> 5, lane = threadIdx.x & 31;
    if (lane == 0) {
        red[warp][0] = ss;
#pragma unroll
        for (int e = 0; e < EE; e++) red[warp][1 + e] = dot[e];
    }
    __syncthreads();
    if (threadIdx.x == 0) {
        float s = 0.f, d[EE];
#pragma unroll
        for (int e = 0; e < EE; e++) d[e] = 0.f;
        for (int w2 = 0; w2 < 8; w2++) {
            s += red[w2][0];
#pragma unroll
            for (int e = 0; e < EE; e++) d[e] += red[w2][1 + e];
        }
        float r = rsqrtf(s / (float)HH + 1.1920929e-7f);
        float lg[EE];
#pragma unroll
        for (int e = 0; e < EE; e++) lg[e] = d[e] * r;
        int i1 = 0;
        for (int e = 1; e < EE; e++) if (lg[e] > lg[i1]) i1 = e;
        int i2 = -1;
        for (int e = 0; e < EE; e++) {
            if (e == i1) continue;
            if (i2 < 0 || lg[e] > lg[i2]) i2 = e;
        }
        float e2 = expf(lg[i2] - lg[i1]);
        float inv = 1.f / (1.f + e2);
        g_tki[t * 2] = i1; g_tki[t * 2 + 1] = i2;
        g_tkw[t * 2] = inv; g_tkw[t * 2 + 1] = e2 * inv;
    }
}

__global__ void dispatch_kernel()
{
    int e = blockIdx.x, tid = threadIdx.x;
    int warp = tid >> 5, lane = tid & 31;
    __shared__ int wsum[8];
    __shared__ int base_s;
    for (int s = tid; s < CAP; s += 256) { g_disp[e*CAP+s] = 0; g_gw[e*CAP+s] = 0.f; }
    if (tid == 0) base_s = 0;
    __syncthreads();
    for (int c0 = 0; c0 < TT; c0 += 256) {
        int t = c0 + tid;
        int i0 = g_tki[t*2], i1 = g_tki[t*2+1];
        float wt = (i0 == e) ? g_tkw[t*2] : ((i1 == e) ? g_tkw[t*2+1] : 0.f);
        int sel = (i0 == e) || (i1 == e);
        unsigned m = __ballot_sync(0xffffffffu, sel);
        int wpre = __popc(m & ((1u << lane) - 1u));
        if (lane == 0) wsum[warp] = __popc(m);
        __syncthreads();
        int woff = 0;
        for (int w = 0; w < warp; w++) woff += wsum[w];
        int slot = base_s + woff + wpre;
        if (sel && slot < CAP) { g_disp[e*CAP+slot] = t; g_gw[e*CAP+slot] = wt; }
        __syncthreads();
        if (tid == 0) {
            int tot = 0;
            for (int w = 0; w < 8; w++) tot += wsum[w];
            base_s += tot;
        }
        __syncthreads();
    }
}

// Fused gate+up, 2-stage, term-major MMA ordering.
template <bool GATHER>
__global__ void __launch_bounds__(256, 2) fused_gateup_k(
    const bf* __restrict__ Ah, const bf* __restrict__ Al,
    const bf* __restrict__ Bgh, const bf* __restrict__ Bgl,
    const bf* __restrict__ Buh, const bf* __restrict__ Bul,
    bf* __restrict__ acth, bf* __restrict__ actl,
    int Kd, int N, size_t sB, size_t sC,
    const int* __restrict__ disp)
{
    extern __shared__ char smem[];
    uint32_t sbu = smem_u32(smem);
    int tid = threadIdx.x, wid = tid >> 5, lane = tid & 31;
    int z = blockIdx.z;
    int bm = blockIdx.y * 128, bn = blockIdx.x * 64;
    int wm = wid & 1, wn = wid >> 1;

    int arw = tid >> 1, ahalf = tid & 1;
    int bkr = tid >> 3, bseg = tid & 7;
    size_t arow;
    if (GATHER) arow = (size_t)disp[z * CAP + bm + arw];
    else        arow = (size_t)(bm + arw);
    const bf* Ahp = Ah + arow * Kd + ahalf * 16;
    const bf* Alp = Al + arow * Kd + ahalf * 16;
    size_t boff = (size_t)z * sB + (size_t)bkr * N + bn + bseg * 8;
    const bf* Bghp = Bgh + boff;
    const bf* Bglp = Bgl + boff;
    const bf* Buhp = Buh + boff;
    const bf* Bulp = Bul + boff;
    uint32_t a_st = (uint32_t)arw * 80u + (uint32_t)ahalf * 32u;
    uint32_t b_st = (uint32_t)bkr * 144u + (uint32_t)bseg * 16u;

    int li = lane & 15, kh = (lane >> 4) << 3;
    uint32_t a_ld = sbu + (uint32_t)(wm * 64 + li) * 80u + (uint32_t)kh * 2u;
    uint32_t b_ld = sbu + (uint32_t)li * 144u + (uint32_t)(wn * 16 + kh) * 2u;

    float accg[4][2][4], accu[4][2][4];
#pragma unroll
    for (int i = 0; i < 4; i++)
#pragma unroll
        for (int j = 0; j < 2; j++)
#pragma unroll
            for (int c = 0; c < 4; c++) { accg[i][j][c] = 0.f; accu[i][j][c] = 0.f; }

    const int NIT = Kd / 32;
    {
        uint32_t sa = sbu + a_st;
        CPA16(sa, Ahp);        CPA16(sa + 16, Ahp + 8);
        CPA16(sa + FA_LO, Alp); CPA16(sa + FA_LO + 16, Alp + 8);
        uint32_t sbb = sbu + b_st;
        CPA16(sbb + FBG_HI, Bghp);
        CPA16(sbb + FBG_LO, Bglp);
        CPA16(sbb + FBU_HI, Buhp);
        CPA16(sbb + FBU_LO, Bulp);
        CPA_COMMIT();
        CPA_WAIT0();
    }
    __syncthreads();

    for (int it = 0; it < NIT; it++) {
        if (it + 1 < NIT) {
            int k0 = (it + 1) * 32;
            uint32_t so = (uint32_t)((it + 1) & 1) * F_BUF;
            uint32_t sa = sbu + so + a_st;
            const bf* ah = Ahp + k0;
            const bf* al = Alp + k0;
            CPA16(sa, ah);         CPA16(sa + 16, ah + 8);
            CPA16(sa + FA_LO, al); CPA16(sa + FA_LO + 16, al + 8);
            uint32_t sbb = sbu + so + b_st;
            size_t go = (size_t)k0 * N;
            CPA16(sbb + FBG_HI, Bghp + go);
            CPA16(sbb + FBG_LO, Bglp + go);
            CPA16(sbb + FBU_HI, Buhp + go);
            CPA16(sbb + FBU_LO, Bulp + go);
            CPA_COMMIT();
        }
        uint32_t bo = (uint32_t)(it & 1) * F_BUF;
#pragma unroll
        for (int k0 = 0; k0 < 32; k0 += 16) {
            uint32_t ah[4][4], al[4][4], bh[4], bl[4];
            uint32_t brow = b_ld + bo + (uint32_t)k0 * 144u;
            // gate B first, then A hi -> early first MMA
            ldsm4t(bh, brow + FBG_HI);
            ldsm4t(bl, brow + FBG_LO);
#pragma unroll
            for (int mt = 0; mt < 4; mt++) {
                uint32_t ad = a_ld + bo + (uint32_t)mt * 1280u + (uint32_t)k0 * 2u;
                ldsm4(ah[mt], ad);
            }
            // gate term1: Ah x Bh (8 independent accs)
#pragma unroll
            for (int mt = 0; mt < 4; mt++)
#pragma unroll
                for (int nt = 0; nt < 2; nt++)
                    mma16816(accg[mt][nt], ah[mt], bh[nt * 2], bh[nt * 2 + 1]);
            // gate term2: Ah x Bl
#pragma unroll
            for (int mt = 0; mt < 4; mt++)
#pragma unroll
                for (int nt = 0; nt < 2; nt++)
                    mma16816(accg[mt][nt], ah[mt], bl[nt * 2], bl[nt * 2 + 1]);
            // load A lo
#pragma unroll
            for (int mt = 0; mt < 4; mt++) {
                uint32_t ad = a_ld + bo + (uint32_t)mt * 1280u + (uint32_t)k0 * 2u;
                ldsm4(al[mt], ad + FA_LO);
            }
            // gate term3: Al x Bh
#pragma unroll
            for (int mt = 0; mt < 4; mt++)
#pragma unroll
                for (int nt = 0; nt < 2; nt++)
                    mma16816(accg[mt][nt], al[mt], bh[nt * 2], bh[nt * 2 + 1]);
            // up B
            ldsm4t(bh, brow + FBU_HI);
            ldsm4t(bl, brow + FBU_LO);
#pragma unroll
            for (int mt = 0; mt < 4; mt++)
#pragma unroll
                for (int nt = 0; nt < 2; nt++)
                    mma16816(accu[mt][nt], ah[mt], bh[nt * 2], bh[nt * 2 + 1]);
#pragma unroll
            for (int mt = 0; mt < 4; mt++)
#pragma unroll
                for (int nt = 0; nt < 2; nt++)
                    mma16816(accu[mt][nt], ah[mt], bl[nt * 2], bl[nt * 2 + 1]);
#pragma unroll
            for (int mt = 0; mt < 4; mt++)
#pragma unroll
                for (int nt = 0; nt < 2; nt++)
                    mma16816(accu[mt][nt], al[mt], bh[nt * 2], bh[nt * 2 + 1]);
        }
        if (it + 1 < NIT) {
            CPA_WAIT0();
            __syncthreads();
        }
    }

    int g = lane >> 2, tg = lane & 3;
#pragma unroll
    for (int mt = 0; mt < 4; mt++) {
#pragma unroll
        for (int nt = 0; nt < 2; nt++) {
            int row0 = bm + wm * 64 + mt * 16 + g;
            int col = bn + wn * 16 + nt * 8 + tg * 2;
            float* dg = accg[mt][nt];
            float* du = accu[mt][nt];
            size_t o0 = (size_t)z * sC + (size_t)row0 * N + col;
            size_t o1 = o0 + (size_t)8 * N;
            float a0 = dg[0] / (1.f + expf(-dg[0])) * du[0];
            float a1 = dg[1] / (1.f + expf(-dg[1])) * du[1];
            float a2 = dg[2] / (1.f + expf(-dg[2])) * du[2];
            float a3 = dg[3] / (1.f + expf(-dg[3])) * du[3];
            __nv_bfloat162 h0 = __floats2bfloat162_rn(a0, a1);
            __nv_bfloat162 h1 = __floats2bfloat162_rn(a2, a3);
            __nv_bfloat162 l0 = __floats2bfloat162_rn(a0 - __bfloat162float(h0.x),
                                                      a1 - __bfloat162float(h0.y));
            __nv_bfloat162 l1 = __floats2bfloat162_rn(a2 - __bfloat162float(h1.x),
                                                      a3 - __bfloat162float(h1.y));
            *(__nv_bfloat162*)(acth + o0) = h0;
            *(__nv_bfloat162*)(acth + o1) = h1;
            *(__nv_bfloat162*)(actl + o0) = l0;
            *(__nv_bfloat162*)(actl + o1) = l1;
        }
    }
}

// Down-proj GEMM, 2-stage, term-major MMA ordering.
template <int EPI>
__global__ void __launch_bounds__(256, 2) hgemm_k(
    const bf* __restrict__ Ah, const bf* __restrict__ Al,
    const bf* __restrict__ Bh, const bf* __restrict__ Bl,
    float* __restrict__ outC,
    int Kd, int N, size_t sA, size_t sB,
    const int* __restrict__ disp, const float* __restrict__ wv)
{
    extern __shared__ char smem[];
    uint32_t sbu = smem_u32(smem);
    int tid = threadIdx.x, wid = tid >> 5, lane = tid & 31;
    int z = blockIdx.z;
    int bm = blockIdx.y * 128, bn = blockIdx.x * 128;
    int wm = wid & 1, wn = wid >> 1;

    int arw = tid >> 1, ahalf = tid & 1;
    int bkr = tid >> 3, bseg = tid & 7;
    const bf* Ahp = Ah + (size_t)z * sA + (size_t)(bm + arw) * Kd + ahalf * 16;
    const bf* Alp = Al + (size_t)z * sA + (size_t)(bm + arw) * Kd + ahalf * 16;
    const bf* Bhp = Bh + (size_t)z * sB + (size_t)bkr * N + bn + bseg * 16;
    const bf* Blp = Bl + (size_t)z * sB + (size_t)bkr * N + bn + bseg * 16;
    uint32_t a_st = (uint32_t)arw * 80u + (uint32_t)ahalf * 32u;
    uint32_t b_st = B_HI + (uint32_t)bkr * 272u + (uint32_t)bseg * 32u;

    int li = lane & 15, kh = (lane >> 4) << 3;
    uint32_t a_ld = sbu + (uint32_t)(wm * 64 + li) * 80u + (uint32_t)kh * 2u;
    uint32_t b_ld = sbu + B_HI + (uint32_t)li * 272u + (uint32_t)(wn * 32 + kh) * 2u;

    float acc[4][4][4];
#pragma unroll
    for (int i = 0; i < 4; i++)
#pragma unroll
        for (int j = 0; j < 4; j++)
#pragma unroll
            for (int c = 0; c < 4; c++) acc[i][j][c] = 0.f;

    const int NIT = Kd / 32;
    {
        uint32_t sa = sbu + a_st, sbb = sbu + b_st;
        CPA16(sa, Ahp);            CPA16(sa + 16, Ahp + 8);
        CPA16(sa + A_LO, Alp);     CPA16(sa + A_LO + 16, Alp + 8);
        CPA16(sbb, Bhp);           CPA16(sbb + 16, Bhp + 8);
        CPA16(sbb + (B_LO - B_HI), Blp); CPA16(sbb + (B_LO - B_HI) + 16, Blp + 8);
        CPA_COMMIT();
        CPA_WAIT0();
    }
    __syncthreads();

    for (int it = 0; it < NIT; it++) {
        if (it + 1 < NIT) {
            int k0 = (it + 1) * 32;
            uint32_t so = (uint32_t)((it + 1) & 1) * SM_BUF;
            uint32_t sa = sbu + so + a_st, sbb = sbu + so + b_st;
            const bf* ah = Ahp + k0;
            const bf* al = Alp + k0;
            const bf* bh = Bhp + (size_t)k0 * N;
            const bf* bl = Blp + (size_t)k0 * N;
            CPA16(sa, ah);            CPA16(sa + 16, ah + 8);
            CPA16(sa + A_LO, al);     CPA16(sa + A_LO + 16, al + 8);
            CPA16(sbb, bh);           CPA16(sbb + 16, bh + 8);
            CPA16(sbb + (B_LO - B_HI), bl); CPA16(sbb + (B_LO - B_HI) + 16, bl + 8);
            CPA_COMMIT();
        }
        uint32_t bo = (uint32_t)(it & 1) * SM_BUF;
#pragma unroll
        for (int k0 = 0; k0 < 32; k0 += 16) {
            uint32_t ah[4][4], al[4][4], bh[4], bl[4];
            uint32_t bd0 = b_ld + bo + (uint32_t)k0 * 272u;
            // np0 B first, then A hi
            ldsm4t(bh, bd0);
            ldsm4t(bl, bd0 + (B_LO - B_HI));
#pragma unroll
            for (int mt = 0; mt < 4; mt++) {
                uint32_t ad = a_ld + bo + (uint32_t)mt * 1280u + (uint32_t)k0 * 2u;
                ldsm4(ah[mt], ad);
            }
            // np0 term1 + term2 (Ah x Bh, Ah x Bl)
#pragma unroll
            for (int mt = 0; mt < 4; mt++)
#pragma unroll
                for (int half = 0; half < 2; half++)
                    mma16816(acc[mt][half], ah[mt], bh[half * 2], bh[half * 2 + 1]);
#pragma unroll
            for (int mt = 0; mt < 4; mt++)
#pragma unroll
                for (int half = 0; half < 2; half++)
                    mma16816(acc[mt][half], ah[mt], bl[half * 2], bl[half * 2 + 1]);
            // A lo
#pragma unroll
            for (int mt = 0; mt < 4; mt++) {
                uint32_t ad = a_ld + bo + (uint32_t)mt * 1280u + (uint32_t)k0 * 2u;
                ldsm4(al[mt], ad + A_LO);
            }
            // np0 term3 (Al x Bh)
#pragma unroll
            for (int mt = 0; mt < 4; mt++)
#pragma unroll
                for (int half = 0; half < 2; half++)
                    mma16816(acc[mt][half], al[mt], bh[half * 2], bh[half * 2 + 1]);
            // np1: reload B frags, reuse A frags
            uint32_t bd1 = bd0 + 32u;
            ldsm4t(bh, bd1);
            ldsm4t(bl, bd1 + (B_LO - B_HI));
#pragma unroll
            for (int mt = 0; mt < 4; mt++)
#pragma unroll
                for (int half = 0; half < 2; half++)
                    mma16816(acc[mt][2 + half], ah[mt], bh[half * 2], bh[half * 2 + 1]);
#pragma unroll
            for (int mt = 0; mt < 4; mt++)
#pragma unroll
                for (int half = 0; half < 2; half++)
                    mma16816(acc[mt][2 + half], ah[mt], bl[half * 2], bl[half * 2 + 1]);
#pragma unroll
            for (int mt = 0; mt < 4; mt++)
#pragma unroll
                for (int half = 0; half < 2; half++)
                    mma16816(acc[mt][2 + half], al[mt], bh[half * 2], bh[half * 2 + 1]);
        }
        if (it + 1 < NIT) {
            CPA_WAIT0();
            __syncthreads();
        }
    }

    int g = lane >> 2, tg = lane & 3;
#pragma unroll
    for (int mt = 0; mt < 4; mt++) {
#pragma unroll
        for (int nt = 0; nt < 4; nt++) {
            int row0 = bm + wm * 64 + mt * 16 + g;
            int col = bn + wn * 32 + nt * 8 + tg * 2;
            float* d = acc[mt][nt];
            if (EPI == 0) {
                float* p0 = outC + (size_t)row0 * N + col;
                float* p1 = p0 + (size_t)8 * N;
                *(float2*)p0 = make_float2(d[0], d[1]);
                *(float2*)p1 = make_float2(d[2], d[3]);
            } else {
                int s0 = z * CAP + row0, s1 = s0 + 8;
                int t0 = disp[s0], t1 = disp[s1];
                float w0 = wv[s0], w1 = wv[s1];
                float* p0 = outC + (size_t)t0 * HH + col;
                float* p1 = outC + (size_t)t1 * HH + col;
                atomicAdd(p0 + 0, w0 * d[0]);
                atomicAdd(p0 + 1, w0 * d[1]);
                atomicAdd(p1 + 0, w1 * d[2]);
                atomicAdd(p1 + 1, w1 * d[3]);
            }
        }
    }
}

extern "C" void kernel_launch(void* const* d_in, const int* in_sizes, int n_in,
                              void* d_out, int out_size)
{
    const float* x  = (const float*)d_in[0];
    const float* rw = (const float*)d_in[1];
    const float* rg = (const float*)d_in[2];
    const float* ru = (const float*)d_in[3];
    const float* rd = (const float*)d_in[4];
    const float* sg = (const float*)d_in[5];
    const float* su = (const float*)d_in[6];
    const float* sd = (const float*)d_in[7];
    float* out = (float*)d_out;

    bf *xh, *xl, *sgh, *sgl, *suh, *sul, *sdh, *sdl, *rgh, *rgl, *ruh, *rul, *rdh, *rdl;
    bf *acth, *actl;
    float *gw;
    int *disp;
    cudaGetSymbolAddress((void**)&xh, g_xh);   cudaGetSymbolAddress((void**)&xl, g_xl);
    cudaGetSymbolAddress((void**)&sgh, g_sgh); cudaGetSymbolAddress((void**)&sgl, g_sgl);
    cudaGetSymbolAddress((void**)&suh, g_suh); cudaGetSymbolAddress((void**)&sul, g_sul);
    cudaGetSymbolAddress((void**)&sdh, g_sdh); cudaGetSymbolAddress((void**)&sdl, g_sdl);
    cudaGetSymbolAddress((void**)&rgh, g_rgh); cudaGetSymbolAddress((void**)&rgl, g_rgl);
    cudaGetSymbolAddress((void**)&ruh, g_ruh); cudaGetSymbolAddress((void**)&rul, g_rul);
    cudaGetSymbolAddress((void**)&rdh, g_rdh); cudaGetSymbolAddress((void**)&rdl, g_rdl);
    cudaGetSymbolAddress((void**)&acth, g_acth); cudaGetSymbolAddress((void**)&actl, g_actl);
    cudaGetSymbolAddress((void**)&gw, g_gw);
    cudaGetSymbolAddress((void**)&disp, g_disp);

    cudaFuncSetAttribute(fused_gateup_k<false>, cudaFuncAttributeMaxDynamicSharedMemorySize, F_TOT);
    cudaFuncSetAttribute(fused_gateup_k<true>,  cudaFuncAttributeMaxDynamicSharedMemorySize, F_TOT);
    cudaFuncSetAttribute(hgemm_k<0>, cudaFuncAttributeMaxDynamicSharedMemorySize, SM_TOT);
    cudaFuncSetAttribute(hgemm_k<2>, cudaFuncAttributeMaxDynamicSharedMemorySize, SM_TOT);

    cvt_split<<<1184, 256>>>(x,  xh,  xl,  (size_t)TT * HH);
    cvt_split<<<1184, 256>>>(sg, sgh, sgl, (size_t)HH * ISS);
    cvt_split<<<1184, 256>>>(su, suh, sul, (size_t)HH * ISS);
    cvt_split<<<1184, 256>>>(sd, sdh, sdl, (size_t)ISS * HH);
    cvt_split<<<1184, 256>>>(rg, rgh, rgl, (size_t)EE * HH * IRR);
    cvt_split<<<1184, 256>>>(ru, ruh, rul, (size_t)EE * HH * IRR);
    cvt_split<<<1184, 256>>>(rd, rdh, rdl, (size_t)EE * IRR * HH);

    router_kernel<<<TT, 256>>>(x, rw);
    dispatch_kernel<<<EE, 256>>>();

    fused_gateup_k<false><<<dim3(ISS / 64, TT / 128, 1), 256, F_TOT>>>(
        xh, xl, sgh, sgl, suh, sul, acth, actl, HH, ISS, 0, 0, (const int*)0);
    hgemm_k<0><<<dim3(HH / 128, TT / 128, 1), 256, SM_TOT>>>(
        acth, actl, sdh, sdl, out, ISS, HH, 0, 0, (const int*)0, (const float*)0);

    fused_gateup_k<true><<<dim3(IRR / 64, CAP / 128, EE), 256, F_TOT>>>(
        xh, xl, rgh, rgl, ruh, rul, acth, actl, HH, IRR,
        (size_t)HH * IRR, (size_t)CAP * IRR, disp);
    hgemm_k<2><<<dim3(HH / 128, CAP / 128, EE), 256, SM_TOT>>>(
        acth, actl, rdh, rdl, out, IRR, HH,
        (size_t)CAP * IRR, (size_t)IRR * HH, disp, gw);
}

// round 16
// speedup vs baseline: 1.0473x; 1.0427x over previous
#include <cuda_runtime.h>
#include <cuda_bf16.h>
#include <math.h>
#include <stdint.h>

#define TT  8192
#define HH  1024
#define EE  8
#define CAP 1280
#define IRR 4096
#define ISS 8192
#define NSPLIT 4

#define A_LO 10240
#define B_HI 20480
#define B_LO 29184
#define SM_BUF 37888
#define SM_TOT (2 * SM_BUF)
#define FA_LO 10240
#define FBG_HI 20480
#define FBG_LO 25088
#define FBU_HI 29696
#define FBU_LO 34304
#define F_BUF 38912
#define F_TOT (2 * F_BUF)

typedef __nv_bfloat16 bf;

__device__ bf g_xh[(size_t)TT * HH],  g_xl[(size_t)TT * HH];
__device__ bf g_sgh[(size_t)HH * ISS], g_sgl[(size_t)HH * ISS];
__device__ bf g_suh[(size_t)HH * ISS], g_sul[(size_t)HH * ISS];
__device__ bf g_sdh[(size_t)ISS * HH], g_sdl[(size_t)ISS * HH];
__device__ bf g_rgh[(size_t)EE * HH * IRR], g_rgl[(size_t)EE * HH * IRR];
__device__ bf g_ruh[(size_t)EE * HH * IRR], g_rul[(size_t)EE * HH * IRR];
__device__ bf g_rdh[(size_t)EE * IRR * HH], g_rdl[(size_t)EE * IRR * HH];
__device__ bf g_acth[(size_t)TT * ISS], g_actl[(size_t)TT * ISS];
__device__ int   g_tki[TT * 2];
__device__ float g_tkw[TT * 2];
__device__ int   g_disp[EE * CAP];
__device__ float g_gw[EE * CAP];

__device__ __forceinline__ uint32_t smem_u32(const void* p) {
    uint32_t a;
    asm("{ .reg .u64 t; cvta.to.shared.u64 t, %1; cvt.u32.u64 %0, t; }" : "=r"(a) : "l"(p));
    return a;
}
__device__ __forceinline__ void ldsm4(uint32_t* r, uint32_t addr) {
    asm volatile("ldmatrix.sync.aligned.m8n8.x4.shared.b16 {%0,%1,%2,%3}, [%4];"
        : "=r"(r[0]), "=r"(r[1]), "=r"(r[2]), "=r"(r[3]) : "r"(addr));
}
__device__ __forceinline__ void ldsm4t(uint32_t* r, uint32_t addr) {
    asm volatile("ldmatrix.sync.aligned.m8n8.x4.trans.shared.b16 {%0,%1,%2,%3}, [%4];"
        : "=r"(r[0]), "=r"(r[1]), "=r"(r[2]), "=r"(r[3]) : "r"(addr));
}
__device__ __forceinline__ void mma16816(float* d, const uint32_t* a, uint32_t b0, uint32_t b1) {
    asm volatile("mma.sync.aligned.m16n8k16.row.col.f32.bf16.bf16.f32 "
        "{%0,%1,%2,%3}, {%4,%5,%6,%7}, {%8,%9}, {%0,%1,%2,%3};"
        : "+f"(d[0]), "+f"(d[1]), "+f"(d[2]), "+f"(d[3])
        : "r"(a[0]), "r"(a[1]), "r"(a[2]), "r"(a[3]), "r"(b0), "r"(b1));
}
#define CPA16(dst, src) asm volatile("cp.async.cg.shared.global [%0], [%1], 16;" :: "r"(dst), "l"(src) : "memory")
#define CPA_COMMIT()    asm volatile("cp.async.commit_group;" ::: "memory")
#define CPA_WAIT0()     asm volatile("cp.async.wait_group 0;" ::: "memory")

__global__ void cvt_split(const float* __restrict__ in, bf* __restrict__ hi,
                          bf* __restrict__ lo, size_t n)
{
    for (size_t i = ((size_t)blockIdx.x * blockDim.x + threadIdx.x) * 4; i < n;
         i += (size_t)gridDim.x * blockDim.x * 4) {
        float4 v = *(const float4*)(in + i);
        __nv_bfloat162 h0 = __floats2bfloat162_rn(v.x, v.y);
        __nv_bfloat162 h1 = __floats2bfloat162_rn(v.z, v.w);
        __nv_bfloat162 l0 = __floats2bfloat162_rn(v.x - __bfloat162float(h0.x),
                                                  v.y - __bfloat162float(h0.y));
        __nv_bfloat162 l1 = __floats2bfloat162_rn(v.z - __bfloat162float(h1.x),
                                                  v.w - __bfloat162float(h1.y));
        *(__nv_bfloat162*)(hi + i) = h0;
        *(__nv_bfloat162*)(hi + i + 2) = h1;
        *(__nv_bfloat162*)(lo + i) = l0;
        *(__nv_bfloat162*)(lo + i + 2) = l1;
    }
}

__global__ void router_kernel(const float* __restrict__ x, const float* __restrict__ rw)
{
    int t = blockIdx.x;
    const float* xr = x + (size_t)t * HH;
    float ss = 0.f, dot[EE];
#pragma unroll
    for (int e = 0; e < EE; e++) dot[e] = 0.f;
    for (int i = threadIdx.x; i < HH; i += 256) {
        float v = xr[i];
        ss += v * v;
#pragma unroll
        for (int e = 0; e < EE; e++) dot[e] += v * rw[e * HH + i];
    }
#pragma unroll
    for (int off = 16; off > 0; off >>= 1) {
        ss += __shfl_down_sync(0xffffffffu, ss, off);
#pragma unroll
        for (int e = 0; e < EE; e++) dot[e] += __shfl_down_sync(0xffffffffu, dot[e], off);
    }
    __shared__ float red[8][9];
    int warp = threadIdx.x >> 5, lane = threadIdx.x & 31;
    if (lane == 0) {
        red[warp][0] = ss;
#pragma unroll
        for (int e = 0; e < EE; e++) red[warp][1 + e] = dot[e];
    }
    __syncthreads();
    if (threadIdx.x == 0) {
        float s = 0.f, d[EE];
#pragma unroll
        for (int e = 0; e < EE; e++) d[e] = 0.f;
        for (int w2 = 0; w2 < 8; w2++) {
            s += red[w2][0];
#pragma unroll
            for (int e = 0; e < EE; e++) d[e] += red[w2][1 + e];
        }
        float r = rsqrtf(s / (float)HH + 1.1920929e-7f);
        float lg[EE];
#pragma unroll
        for (int e = 0; e < EE; e++) lg[e] = d[e] * r;
        int i1 = 0;
        for (int e = 1; e < EE; e++) if (lg[e] > lg[i1]) i1 = e;
        int i2 = -1;
        for (int e = 0; e < EE; e++) {
            if (e == i1) continue;
            if (i2 < 0 || lg[e] > lg[i2]) i2 = e;
        }
        float e2 = expf(lg[i2] - lg[i1]);
        float inv = 1.f / (1.f + e2);
        g_tki[t * 2] = i1; g_tki[t * 2 + 1] = i2;
        g_tkw[t * 2] = inv; g_tkw[t * 2 + 1] = e2 * inv;
    }
}

__global__ void dispatch_kernel()
{
    int e = blockIdx.x, tid = threadIdx.x;
    int warp = tid >> 5, lane = tid & 31;
    __shared__ int wsum[8];
    __shared__ int base_s;
    for (int s = tid; s < CAP; s += 256) { g_disp[e*CAP+s] = 0; g_gw[e*CAP+s] = 0.f; }
    if (tid == 0) base_s = 0;
    __syncthreads();
    for (int c0 = 0; c0 < TT; c0 += 256) {
        int t = c0 + tid;
        int i0 = g_tki[t*2], i1 = g_tki[t*2+1];
        float wt = (i0 == e) ? g_tkw[t*2] : ((i1 == e) ? g_tkw[t*2+1] : 0.f);
        int sel = (i0 == e) || (i1 == e);
        unsigned m = __ballot_sync(0xffffffffu, sel);
        int wpre = __popc(m & ((1u << lane) - 1u));
        if (lane == 0) wsum[warp] = __popc(m);
        __syncthreads();
        int woff = 0;
        for (int w = 0; w < warp; w++) woff += wsum[w];
        int slot = base_s + woff + wpre;
        if (sel && slot < CAP) { g_disp[e*CAP+slot] = t; g_gw[e*CAP+slot] = wt; }
        __syncthreads();
        if (tid == 0) {
            int tot = 0;
            for (int w = 0; w < 8; w++) tot += wsum[w];
            base_s += tot;
        }
        __syncthreads();
    }
}

// Fused gate+up (unchanged from R15).
template <bool GATHER>
__global__ void __launch_bounds__(256, 2) fused_gateup_k(
    const bf* __restrict__ Ah, const bf* __restrict__ Al,
    const bf* __restrict__ Bgh, const bf* __restrict__ Bgl,
    const bf* __restrict__ Buh, const bf* __restrict__ Bul,
    bf* __restrict__ acth, bf* __restrict__ actl,
    int Kd, int N, size_t sB, size_t sC,
    const int* __restrict__ disp)
{
    extern __shared__ char smem[];
    uint32_t sbu = smem_u32(smem);
    int tid = threadIdx.x, wid = tid >> 5, lane = tid & 31;
    int z = blockIdx.z;
    int bm = blockIdx.y * 128, bn = blockIdx.x * 64;
    int wm = wid & 1, wn = wid >> 1;

    int arw = tid >> 1, ahalf = tid & 1;
    int bkr = tid >> 3, bseg = tid & 7;
    size_t arow;
    if (GATHER) arow = (size_t)disp[z * CAP + bm + arw];
    else        arow = (size_t)(bm + arw);
    const bf* Ahp = Ah + arow * Kd + ahalf * 16;
    const bf* Alp = Al + arow * Kd + ahalf * 16;
    size_t boff = (size_t)z * sB + (size_t)bkr * N + bn + bseg * 8;
    const bf* Bghp = Bgh + boff;
    const bf* Bglp = Bgl + boff;
    const bf* Buhp = Buh + boff;
    const bf* Bulp = Bul + boff;
    uint32_t a_st = (uint32_t)arw * 80u + (uint32_t)ahalf * 32u;
    uint32_t b_st = (uint32_t)bkr * 144u + (uint32_t)bseg * 16u;

    int li = lane & 15, kh = (lane >> 4) << 3;
    uint32_t a_ld = sbu + (uint32_t)(wm * 64 + li) * 80u + (uint32_t)kh * 2u;
    uint32_t b_ld = sbu + (uint32_t)li * 144u + (uint32_t)(wn * 16 + kh) * 2u;

    float accg[4][2][4], accu[4][2][4];
#pragma unroll
    for (int i = 0; i < 4; i++)
#pragma unroll
        for (int j = 0; j < 2; j++)
#pragma unroll
            for (int c = 0; c < 4; c++) { accg[i][j][c] = 0.f; accu[i][j][c] = 0.f; }

    const int NIT = Kd / 32;
    {
        uint32_t sa = sbu + a_st;
        CPA16(sa, Ahp);        CPA16(sa + 16, Ahp + 8);
        CPA16(sa + FA_LO, Alp); CPA16(sa + FA_LO + 16, Alp + 8);
        uint32_t sbb = sbu + b_st;
        CPA16(sbb + FBG_HI, Bghp);
        CPA16(sbb + FBG_LO, Bglp);
        CPA16(sbb + FBU_HI, Buhp);
        CPA16(sbb + FBU_LO, Bulp);
        CPA_COMMIT();
        CPA_WAIT0();
    }
    __syncthreads();

    for (int it = 0; it < NIT; it++) {
        if (it + 1 < NIT) {
            int k0 = (it + 1) * 32;
            uint32_t so = (uint32_t)((it + 1) & 1) * F_BUF;
            uint32_t sa = sbu + so + a_st;
            const bf* ah = Ahp + k0;
            const bf* al = Alp + k0;
            CPA16(sa, ah);         CPA16(sa + 16, ah + 8);
            CPA16(sa + FA_LO, al); CPA16(sa + FA_LO + 16, al + 8);
            uint32_t sbb = sbu + so + b_st;
            size_t go = (size_t)k0 * N;
            CPA16(sbb + FBG_HI, Bghp + go);
            CPA16(sbb + FBG_LO, Bglp + go);
            CPA16(sbb + FBU_HI, Buhp + go);
            CPA16(sbb + FBU_LO, Bulp + go);
            CPA_COMMIT();
        }
        uint32_t bo = (uint32_t)(it & 1) * F_BUF;
#pragma unroll
        for (int k0 = 0; k0 < 32; k0 += 16) {
            uint32_t ah[4][4], al[4][4], bh[4], bl[4];
            uint32_t brow = b_ld + bo + (uint32_t)k0 * 144u;
            ldsm4t(bh, brow + FBG_HI);
            ldsm4t(bl, brow + FBG_LO);
#pragma unroll
            for (int mt = 0; mt < 4; mt++) {
                uint32_t ad = a_ld + bo + (uint32_t)mt * 1280u + (uint32_t)k0 * 2u;
                ldsm4(ah[mt], ad);
            }
#pragma unroll
            for (int mt = 0; mt < 4; mt++)
#pragma unroll
                for (int nt = 0; nt < 2; nt++)
                    mma16816(accg[mt][nt], ah[mt], bh[nt * 2], bh[nt * 2 + 1]);
#pragma unroll
            for (int mt = 0; mt < 4; mt++)
#pragma unroll
                for (int nt = 0; nt < 2; nt++)
                    mma16816(accg[mt][nt], ah[mt], bl[nt * 2], bl[nt * 2 + 1]);
#pragma unroll
            for (int mt = 0; mt < 4; mt++) {
                uint32_t ad = a_ld + bo + (uint32_t)mt * 1280u + (uint32_t)k0 * 2u;
                ldsm4(al[mt], ad + FA_LO);
            }
#pragma unroll
            for (int mt = 0; mt < 4; mt++)
#pragma unroll
                for (int nt = 0; nt < 2; nt++)
                    mma16816(accg[mt][nt], al[mt], bh[nt * 2], bh[nt * 2 + 1]);
            ldsm4t(bh, brow + FBU_HI);
            ldsm4t(bl, brow + FBU_LO);
#pragma unroll
            for (int mt = 0; mt < 4; mt++)
#pragma unroll
                for (int nt = 0; nt < 2; nt++)
                    mma16816(accu[mt][nt], ah[mt], bh[nt * 2], bh[nt * 2 + 1]);
#pragma unroll
            for (int mt = 0; mt < 4; mt++)
#pragma unroll
                for (int nt = 0; nt < 2; nt++)
                    mma16816(accu[mt][nt], ah[mt], bl[nt * 2], bl[nt * 2 + 1]);
#pragma unroll
            for (int mt = 0; mt < 4; mt++)
#pragma unroll
                for (int nt = 0; nt < 2; nt++)
                    mma16816(accu[mt][nt], al[mt], bh[nt * 2], bh[nt * 2 + 1]);
        }
        if (it + 1 < NIT) {
            CPA_WAIT0();
            __syncthreads();
        }
    }

    int g = lane >> 2, tg = lane & 3;
#pragma unroll
    for (int mt = 0; mt < 4; mt++) {
#pragma unroll
        for (int nt = 0; nt < 2; nt++) {
            int row0 = bm + wm * 64 + mt * 16 + g;
            int col = bn + wn * 16 + nt * 8 + tg * 2;
            float* dg = accg[mt][nt];
            float* du = accu[mt][nt];
            size_t o0 = (size_t)z * sC + (size_t)row0 * N + col;
            size_t o1 = o0 + (size_t)8 * N;
            float a0 = dg[0] / (1.f + expf(-dg[0])) * du[0];
            float a1 = dg[1] / (1.f + expf(-dg[1])) * du[1];
            float a2 = dg[2] / (1.f + expf(-dg[2])) * du[2];
            float a3 = dg[3] / (1.f + expf(-dg[3])) * du[3];
            __nv_bfloat162 h0 = __floats2bfloat162_rn(a0, a1);
            __nv_bfloat162 h1 = __floats2bfloat162_rn(a2, a3);
            __nv_bfloat162 l0 = __floats2bfloat162_rn(a0 - __bfloat162float(h0.x),
                                                      a1 - __bfloat162float(h0.y));
            __nv_bfloat162 l1 = __floats2bfloat162_rn(a2 - __bfloat162float(h1.x),
                                                      a3 - __bfloat162float(h1.y));
            *(__nv_bfloat162*)(acth + o0) = h0;
            *(__nv_bfloat162*)(acth + o1) = h1;
            *(__nv_bfloat162*)(actl + o0) = l0;
            *(__nv_bfloat162*)(actl + o1) = l1;
        }
    }
}

// Down-proj GEMM with split-K. z = expert * NSPLIT + slice.
// EPI 0: atomicAdd to outC rows; EPI 2: weighted atomic scatter via disp.
template <int EPI>
__global__ void __launch_bounds__(256, 2) hgemm_k(
    const bf* __restrict__ Ah, const bf* __restrict__ Al,
    const bf* __restrict__ Bh, const bf* __restrict__ Bl,
    float* __restrict__ outC,
    int Kfull, int N, size_t sA, size_t sB,
    const int* __restrict__ disp, const float* __restrict__ wv)
{
    extern __shared__ char smem[];
    uint32_t sbu = smem_u32(smem);
    int tid = threadIdx.x, wid = tid >> 5, lane = tid & 31;
    int zexp = blockIdx.z / NSPLIT, zs = blockIdx.z % NSPLIT;
    int Ksl = Kfull / NSPLIT;
    int koff = zs * Ksl;
    int bm = blockIdx.y * 128, bn = blockIdx.x * 128;
    int wm = wid & 1, wn = wid >> 1;

    int arw = tid >> 1, ahalf = tid & 1;
    int bkr = tid >> 3, bseg = tid & 7;
    const bf* Ahp = Ah + (size_t)zexp * sA + (size_t)(bm + arw) * Kfull + koff + ahalf * 16;
    const bf* Alp = Al + (size_t)zexp * sA + (size_t)(bm + arw) * Kfull + koff + ahalf * 16;
    const bf* Bhp = Bh + (size_t)zexp * sB + (size_t)(koff + bkr) * N + bn + bseg * 16;
    const bf* Blp = Bl + (size_t)zexp * sB + (size_t)(koff + bkr) * N + bn + bseg * 16;
    uint32_t a_st = (uint32_t)arw * 80u + (uint32_t)ahalf * 32u;
    uint32_t b_st = B_HI + (uint32_t)bkr * 272u + (uint32_t)bseg * 32u;

    int li = lane & 15, kh = (lane >> 4) << 3;
    uint32_t a_ld = sbu + (uint32_t)(wm * 64 + li) * 80u + (uint32_t)kh * 2u;
    uint32_t b_ld = sbu + B_HI + (uint32_t)li * 272u + (uint32_t)(wn * 32 + kh) * 2u;

    float acc[4][4][4];
#pragma unroll
    for (int i = 0; i < 4; i++)
#pragma unroll
        for (int j = 0; j < 4; j++)
#pragma unroll
            for (int c = 0; c < 4; c++) acc[i][j][c] = 0.f;

    const int NIT = Ksl / 32;
    {
        uint32_t sa = sbu + a_st, sbb = sbu + b_st;
        CPA16(sa, Ahp);            CPA16(sa + 16, Ahp + 8);
        CPA16(sa + A_LO, Alp);     CPA16(sa + A_LO + 16, Alp + 8);
        CPA16(sbb, Bhp);           CPA16(sbb + 16, Bhp + 8);
        CPA16(sbb + (B_LO - B_HI), Blp); CPA16(sbb + (B_LO - B_HI) + 16, Blp + 8);
        CPA_COMMIT();
        CPA_WAIT0();
    }
    __syncthreads();

    for (int it = 0; it < NIT; it++) {
        if (it + 1 < NIT) {
            int k0 = (it + 1) * 32;
            uint32_t so = (uint32_t)((it + 1) & 1) * SM_BUF;
            uint32_t sa = sbu + so + a_st, sbb = sbu + so + b_st;
            const bf* ah = Ahp + k0;
            const bf* al = Alp + k0;
            const bf* bh = Bhp + (size_t)k0 * N;
            const bf* bl = Blp + (size_t)k0 * N;
            CPA16(sa, ah);            CPA16(sa + 16, ah + 8);
            CPA16(sa + A_LO, al);     CPA16(sa + A_LO + 16, al + 8);
            CPA16(sbb, bh);           CPA16(sbb + 16, bh + 8);
            CPA16(sbb + (B_LO - B_HI), bl); CPA16(sbb + (B_LO - B_HI) + 16, bl + 8);
            CPA_COMMIT();
        }
        uint32_t bo = (uint32_t)(it & 1) * SM_BUF;
#pragma unroll
        for (int k0 = 0; k0 < 32; k0 += 16) {
            uint32_t ah[4][4], al[4][4], bh[4], bl[4];
            uint32_t bd0 = b_ld + bo + (uint32_t)k0 * 272u;
            ldsm4t(bh, bd0);
            ldsm4t(bl, bd0 + (B_LO - B_HI));
#pragma unroll
            for (int mt = 0; mt < 4; mt++) {
                uint32_t ad = a_ld + bo + (uint32_t)mt * 1280u + (uint32_t)k0 * 2u;
                ldsm4(ah[mt], ad);
            }
#pragma unroll
            for (int mt = 0; mt < 4; mt++)
#pragma unroll
                for (int half = 0; half < 2; half++)
                    mma16816(acc[mt][half], ah[mt], bh[half * 2], bh[half * 2 + 1]);
#pragma unroll
            for (int mt = 0; mt < 4; mt++)
#pragma unroll
                for (int half = 0; half < 2; half++)
                    mma16816(acc[mt][half], ah[mt], bl[half * 2], bl[half * 2 + 1]);
#pragma unroll
            for (int mt = 0; mt < 4; mt++) {
                uint32_t ad = a_ld + bo + (uint32_t)mt * 1280u + (uint32_t)k0 * 2u;
                ldsm4(al[mt], ad + A_LO);
            }
#pragma unroll
            for (int mt = 0; mt < 4; mt++)
#pragma unroll
                for (int half = 0; half < 2; half++)
                    mma16816(acc[mt][half], al[mt], bh[half * 2], bh[half * 2 + 1]);
            uint32_t bd1 = bd0 + 32u;
            ldsm4t(bh, bd1);
            ldsm4t(bl, bd1 + (B_LO - B_HI));
#pragma unroll
            for (int mt = 0; mt < 4; mt++)
#pragma unroll
                for (int half = 0; half < 2; half++)
                    mma16816(acc[mt][2 + half], ah[mt], bh[half * 2], bh[half * 2 + 1]);
#pragma unroll
            for (int mt = 0; mt < 4; mt++)
#pragma unroll
                for (int half = 0; half < 2; half++)
                    mma16816(acc[mt][2 + half], ah[mt], bl[half * 2], bl[half * 2 + 1]);
#pragma unroll
            for (int mt = 0; mt < 4; mt++)
#pragma unroll
                for (int half = 0; half < 2; half++)
                    mma16816(acc[mt][2 + half], al[mt], bh[half * 2], bh[half * 2 + 1]);
        }
        if (it + 1 < NIT) {
            CPA_WAIT0();
            __syncthreads();
        }
    }

    int g = lane >> 2, tg = lane & 3;
#pragma unroll
    for (int mt = 0; mt < 4; mt++) {
#pragma unroll
        for (int nt = 0; nt < 4; nt++) {
            int row0 = bm + wm * 64 + mt * 16 + g;
            int col = bn + wn * 32 + nt * 8 + tg * 2;
            float* d = acc[mt][nt];
            if (EPI == 0) {
                float* p0 = outC + (size_t)row0 * N + col;
                float* p1 = p0 + (size_t)8 * N;
                atomicAdd(p0 + 0, d[0]);
                atomicAdd(p0 + 1, d[1]);
                atomicAdd(p1 + 0, d[2]);
                atomicAdd(p1 + 1, d[3]);
            } else {
                int s0 = zexp * CAP + row0, s1 = s0 + 8;
                int t0 = disp[s0], t1 = disp[s1];
                float w0 = wv[s0], w1 = wv[s1];
                float* p0 = outC + (size_t)t0 * HH + col;
                float* p1 = outC + (size_t)t1 * HH + col;
                atomicAdd(p0 + 0, w0 * d[0]);
                atomicAdd(p0 + 1, w0 * d[1]);
                atomicAdd(p1 + 0, w1 * d[2]);
                atomicAdd(p1 + 1, w1 * d[3]);
            }
        }
    }
}

extern "C" void kernel_launch(void* const* d_in, const int* in_sizes, int n_in,
                              void* d_out, int out_size)
{
    const float* x  = (const float*)d_in[0];
    const float* rw = (const float*)d_in[1];
    const float* rg = (const float*)d_in[2];
    const float* ru = (const float*)d_in[3];
    const float* rd = (const float*)d_in[4];
    const float* sg = (const float*)d_in[5];
    const float* su = (const float*)d_in[6];
    const float* sd = (const float*)d_in[7];
    float* out = (float*)d_out;

    bf *xh, *xl, *sgh, *sgl, *suh, *sul, *sdh, *sdl, *rgh, *rgl, *ruh, *rul, *rdh, *rdl;
    bf *acth, *actl;
    float *gw;
    int *disp;
    cudaGetSymbolAddress((void**)&xh, g_xh);   cudaGetSymbolAddress((void**)&xl, g_xl);
    cudaGetSymbolAddress((void**)&sgh, g_sgh); cudaGetSymbolAddress((void**)&sgl, g_sgl);
    cudaGetSymbolAddress((void**)&suh, g_suh); cudaGetSymbolAddress((void**)&sul, g_sul);
    cudaGetSymbolAddress((void**)&sdh, g_sdh); cudaGetSymbolAddress((void**)&sdl, g_sdl);
    cudaGetSymbolAddress((void**)&rgh, g_rgh); cudaGetSymbolAddress((void**)&rgl, g_rgl);
    cudaGetSymbolAddress((void**)&ruh, g_ruh); cudaGetSymbolAddress((void**)&rul, g_rul);
    cudaGetSymbolAddress((void**)&rdh, g_rdh); cudaGetSymbolAddress((void**)&rdl, g_rdl);
    cudaGetSymbolAddress((void**)&acth, g_acth); cudaGetSymbolAddress((void**)&actl, g_actl);
    cudaGetSymbolAddress((void**)&gw, g_gw);
    cudaGetSymbolAddress((void**)&disp, g_disp);

    cudaFuncSetAttribute(fused_gateup_k<false>, cudaFuncAttributeMaxDynamicSharedMemorySize, F_TOT);
    cudaFuncSetAttribute(fused_gateup_k<true>,  cudaFuncAttributeMaxDynamicSharedMemorySize, F_TOT);
    cudaFuncSetAttribute(hgemm_k<0>, cudaFuncAttributeMaxDynamicSharedMemorySize, SM_TOT);
    cudaFuncSetAttribute(hgemm_k<2>, cudaFuncAttributeMaxDynamicSharedMemorySize, SM_TOT);

    cvt_split<<<1184, 256>>>(x,  xh,  xl,  (size_t)TT * HH);
    cvt_split<<<1184, 256>>>(sg, sgh, sgl, (size_t)HH * ISS);
    cvt_split<<<1184, 256>>>(su, suh, sul, (size_t)HH * ISS);
    cvt_split<<<1184, 256>>>(sd, sdh, sdl, (size_t)ISS * HH);
    cvt_split<<<1184, 256>>>(rg, rgh, rgl, (size_t)EE * HH * IRR);
    cvt_split<<<1184, 256>>>(ru, ruh, rul, (size_t)EE * HH * IRR);
    cvt_split<<<1184, 256>>>(rd, rdh, rdl, (size_t)EE * IRR * HH);

    router_kernel<<<TT, 256>>>(x, rw);
    dispatch_kernel<<<EE, 256>>>();
    cudaMemsetAsync(out, 0, (size_t)TT * HH * sizeof(float));

    fused_gateup_k<false><<<dim3(ISS / 64, TT / 128, 1), 256, F_TOT>>>(
        xh, xl, sgh, sgl, suh, sul, acth, actl, HH, ISS, 0, 0, (const int*)0);
    hgemm_k<0><<<dim3(HH / 128, TT / 128, NSPLIT), 256, SM_TOT>>>(
        acth, actl, sdh, sdl, out, ISS, HH, 0, 0, (const int*)0, (const float*)0);

    fused_gateup_k<true><<<dim3(IRR / 64, CAP / 128, EE), 256, F_TOT>>>(
        xh, xl, rgh, rgl, ruh, rul, acth, actl, HH, IRR,
        (size_t)HH * IRR, (size_t)CAP * IRR, disp);
    hgemm_k<2><<<dim3(HH / 128, CAP / 128, EE * NSPLIT), 256, SM_TOT>>>(
        acth, actl, rdh, rdl, out, IRR, HH,
        (size_t)CAP * IRR, (size_t)IRR * HH, disp, gw);
}

// round 17
// speedup vs baseline: 1.0720x; 1.0235x over previous
#include <cuda_runtime.h>
#include <cuda_bf16.h>
#include <math.h>
#include <stdint.h>

#define TT  8192
#define HH  1024
#define EE  8
#define CAP 1280
#define IRR 4096
#define ISS 8192
#define NSPLIT 4

#define A_LO 10240
#define B_HI 20480
#define B_LO 29184
#define SM_BUF 37888
#define SM_TOT (2 * SM_BUF)
#define FA_LO 10240
#define FBG_HI 20480
#define FBG_LO 25088
#define FBU_HI 29696
#define FBU_LO 34304
#define F_BUF 38912
#define F_TOT (2 * F_BUF)

typedef __nv_bfloat16 bf;

__device__ bf g_xh[(size_t)TT * HH],  g_xl[(size_t)TT * HH];
__device__ bf g_sgh[(size_t)HH * ISS], g_sgl[(size_t)HH * ISS];
__device__ bf g_suh[(size_t)HH * ISS], g_sul[(size_t)HH * ISS];
__device__ bf g_sdh[(size_t)ISS * HH], g_sdl[(size_t)ISS * HH];
__device__ bf g_rgh[(size_t)EE * HH * IRR], g_rgl[(size_t)EE * HH * IRR];
__device__ bf g_ruh[(size_t)EE * HH * IRR], g_rul[(size_t)EE * HH * IRR];
__device__ bf g_rdh[(size_t)EE * IRR * HH], g_rdl[(size_t)EE * IRR * HH];
__device__ bf g_acth[(size_t)TT * ISS], g_actl[(size_t)TT * ISS];
__device__ bf g_racth[(size_t)EE * CAP * IRR], g_ractl[(size_t)EE * CAP * IRR];
__device__ int   g_tki[TT * 2];
__device__ float g_tkw[TT * 2];
__device__ int   g_disp[EE * CAP];
__device__ float g_gw[EE * CAP];

__device__ __forceinline__ uint32_t smem_u32(const void* p) {
    uint32_t a;
    asm("{ .reg .u64 t; cvta.to.shared.u64 t, %1; cvt.u32.u64 %0, t; }" : "=r"(a) : "l"(p));
    return a;
}
__device__ __forceinline__ void ldsm4(uint32_t* r, uint32_t addr) {
    asm volatile("ldmatrix.sync.aligned.m8n8.x4.shared.b16 {%0,%1,%2,%3}, [%4];"
        : "=r"(r[0]), "=r"(r[1]), "=r"(r[2]), "=r"(r[3]) : "r"(addr));
}
__device__ __forceinline__ void ldsm4t(uint32_t* r, uint32_t addr) {
    asm volatile("ldmatrix.sync.aligned.m8n8.x4.trans.shared.b16 {%0,%1,%2,%3}, [%4];"
        : "=r"(r[0]), "=r"(r[1]), "=r"(r[2]), "=r"(r[3]) : "r"(addr));
}
__device__ __forceinline__ void mma16816(float* d, const uint32_t* a, uint32_t b0, uint32_t b1) {
    asm volatile("mma.sync.aligned.m16n8k16.row.col.f32.bf16.bf16.f32 "
        "{%0,%1,%2,%3}, {%4,%5,%6,%7}, {%8,%9}, {%0,%1,%2,%3};"
        : "+f"(d[0]), "+f"(d[1]), "+f"(d[2]), "+f"(d[3])
        : "r"(a[0]), "r"(a[1]), "r"(a[2]), "r"(a[3]), "r"(b0), "r"(b1));
}
#define CPA16(dst, src) asm volatile("cp.async.cg.shared.global [%0], [%1], 16;" :: "r"(dst), "l"(src) : "memory")
#define CPA_COMMIT()    asm volatile("cp.async.commit_group;" ::: "memory")
#define CPA_WAIT0()     asm volatile("cp.async.wait_group 0;" ::: "memory")

__global__ void cvt_split(const float* __restrict__ in, bf* __restrict__ hi,
                          bf* __restrict__ lo, size_t n)
{
    for (size_t i = ((size_t)blockIdx.x * blockDim.x + threadIdx.x) * 4; i < n;
         i += (size_t)gridDim.x * blockDim.x * 4) {
        float4 v = *(const float4*)(in + i);
        __nv_bfloat162 h0 = __floats2bfloat162_rn(v.x, v.y);
        __nv_bfloat162 h1 = __floats2bfloat162_rn(v.z, v.w);
        __nv_bfloat162 l0 = __floats2bfloat162_rn(v.x - __bfloat162float(h0.x),
                                                  v.y - __bfloat162float(h0.y));
        __nv_bfloat162 l1 = __floats2bfloat162_rn(v.z - __bfloat162float(h1.x),
                                                  v.w - __bfloat162float(h1.y));
        *(__nv_bfloat162*)(hi + i) = h0;
        *(__nv_bfloat162*)(hi + i + 2) = h1;
        *(__nv_bfloat162*)(lo + i) = l0;
        *(__nv_bfloat162*)(lo + i + 2) = l1;
    }
}

__global__ void router_kernel(const float* __restrict__ x, const float* __restrict__ rw)
{
    int t = blockIdx.x;
    const float* xr = x + (size_t)t * HH;
    float ss = 0.f, dot[EE];
#pragma unroll
    for (int e = 0; e < EE; e++) dot[e] = 0.f;
    for (int i = threadIdx.x; i < HH; i += 256) {
        float v = xr[i];
        ss += v * v;
#pragma unroll
        for (int e = 0; e < EE; e++) dot[e] += v * rw[e * HH + i];
    }
#pragma unroll
    for (int off = 16; off > 0; off >>= 1) {
        ss += __shfl_down_sync(0xffffffffu, ss, off);
#pragma unroll
        for (int e = 0; e < EE; e++) dot[e] += __shfl_down_sync(0xffffffffu, dot[e], off);
    }
    __shared__ float red[8][9];
    int warp = threadIdx.x >> 5, lane = threadIdx.x & 31;
    if (lane == 0) {
        red[warp][0] = ss;
#pragma unroll
        for (int e = 0; e < EE; e++) red[warp][1 + e] = dot[e];
    }
    __syncthreads();
    if (threadIdx.x == 0) {
        float s = 0.f, d[EE];
#pragma unroll
        for (int e = 0; e < EE; e++) d[e] = 0.f;
        for (int w2 = 0; w2 < 8; w2++) {
            s += red[w2][0];
#pragma unroll
            for (int e = 0; e < EE; e++) d[e] += red[w2][1 + e];
        }
        float r = rsqrtf(s / (float)HH + 1.1920929e-7f);
        float lg[EE];
#pragma unroll
        for (int e = 0; e < EE; e++) lg[e] = d[e] * r;
        int i1 = 0;
        for (int e = 1; e < EE; e++) if (lg[e] > lg[i1]) i1 = e;
        int i2 = -1;
        for (int e = 0; e < EE; e++) {
            if (e == i1) continue;
            if (i2 < 0 || lg[e] > lg[i2]) i2 = e;
        }
        float e2 = expf(lg[i2] - lg[i1]);
        float inv = 1.f / (1.f + e2);
        g_tki[t * 2] = i1; g_tki[t * 2 + 1] = i2;
        g_tkw[t * 2] = inv; g_tkw[t * 2 + 1] = e2 * inv;
    }
}

__global__ void dispatch_kernel()
{
    int e = blockIdx.x, tid = threadIdx.x;
    int warp = tid >> 5, lane = tid & 31;
    __shared__ int wsum[8];
    __shared__ int base_s;
    for (int s = tid; s < CAP; s += 256) { g_disp[e*CAP+s] = 0; g_gw[e*CAP+s] = 0.f; }
    if (tid == 0) base_s = 0;
    __syncthreads();
    for (int c0 = 0; c0 < TT; c0 += 256) {
        int t = c0 + tid;
        int i0 = g_tki[t*2], i1 = g_tki[t*2+1];
        float wt = (i0 == e) ? g_tkw[t*2] : ((i1 == e) ? g_tkw[t*2+1] : 0.f);
        int sel = (i0 == e) || (i1 == e);
        unsigned m = __ballot_sync(0xffffffffu, sel);
        int wpre = __popc(m & ((1u << lane) - 1u));
        if (lane == 0) wsum[warp] = __popc(m);
        __syncthreads();
        int woff = 0;
        for (int w = 0; w < warp; w++) woff += wsum[w];
        int slot = base_s + woff + wpre;
        if (sel && slot < CAP) { g_disp[e*CAP+slot] = t; g_gw[e*CAP+slot] = wt; }
        __syncthreads();
        if (tid == 0) {
            int tot = 0;
            for (int w = 0; w < 8; w++) tot += wsum[w];
            base_s += tot;
        }
        __syncthreads();
    }
}

template <bool GATHER>
__global__ void __launch_bounds__(256, 2) fused_gateup_k(
    const bf* __restrict__ Ah, const bf* __restrict__ Al,
    const bf* __restrict__ Bgh, const bf* __restrict__ Bgl,
    const bf* __restrict__ Buh, const bf* __restrict__ Bul,
    bf* __restrict__ acth, bf* __restrict__ actl,
    int Kd, int N, size_t sB, size_t sC,
    const int* __restrict__ disp)
{
    extern __shared__ char smem[];
    uint32_t sbu = smem_u32(smem);
    int tid = threadIdx.x, wid = tid >> 5, lane = tid & 31;
    int z = blockIdx.z;
    int bm = blockIdx.y * 128, bn = blockIdx.x * 64;
    int wm = wid & 1, wn = wid >> 1;

    int arw = tid >> 1, ahalf = tid & 1;
    int bkr = tid >> 3, bseg = tid & 7;
    size_t arow;
    if (GATHER) arow = (size_t)disp[z * CAP + bm + arw];
    else        arow = (size_t)(bm + arw);
    const bf* Ahp = Ah + arow * Kd + ahalf * 16;
    const bf* Alp = Al + arow * Kd + ahalf * 16;
    size_t boff = (size_t)z * sB + (size_t)bkr * N + bn + bseg * 8;
    const bf* Bghp = Bgh + boff;
    const bf* Bglp = Bgl + boff;
    const bf* Buhp = Buh + boff;
    const bf* Bulp = Bul + boff;
    uint32_t a_st = (uint32_t)arw * 80u + (uint32_t)ahalf * 32u;
    uint32_t b_st = (uint32_t)bkr * 144u + (uint32_t)bseg * 16u;

    int li = lane & 15, kh = (lane >> 4) << 3;
    uint32_t a_ld = sbu + (uint32_t)(wm * 64 + li) * 80u + (uint32_t)kh * 2u;
    uint32_t b_ld = sbu + (uint32_t)li * 144u + (uint32_t)(wn * 16 + kh) * 2u;

    float accg[4][2][4], accu[4][2][4];
#pragma unroll
    for (int i = 0; i < 4; i++)
#pragma unroll
        for (int j = 0; j < 2; j++)
#pragma unroll
            for (int c = 0; c < 4; c++) { accg[i][j][c] = 0.f; accu[i][j][c] = 0.f; }

    const int NIT = Kd / 32;
    {
        uint32_t sa = sbu + a_st;
        CPA16(sa, Ahp);        CPA16(sa + 16, Ahp + 8);
        CPA16(sa + FA_LO, Alp); CPA16(sa + FA_LO + 16, Alp + 8);
        uint32_t sbb = sbu + b_st;
        CPA16(sbb + FBG_HI, Bghp);
        CPA16(sbb + FBG_LO, Bglp);
        CPA16(sbb + FBU_HI, Buhp);
        CPA16(sbb + FBU_LO, Bulp);
        CPA_COMMIT();
        CPA_WAIT0();
    }
    __syncthreads();

    for (int it = 0; it < NIT; it++) {
        if (it + 1 < NIT) {
            int k0 = (it + 1) * 32;
            uint32_t so = (uint32_t)((it + 1) & 1) * F_BUF;
            uint32_t sa = sbu + so + a_st;
            const bf* ah = Ahp + k0;
            const bf* al = Alp + k0;
            CPA16(sa, ah);         CPA16(sa + 16, ah + 8);
            CPA16(sa + FA_LO, al); CPA16(sa + FA_LO + 16, al + 8);
            uint32_t sbb = sbu + so + b_st;
            size_t go = (size_t)k0 * N;
            CPA16(sbb + FBG_HI, Bghp + go);
            CPA16(sbb + FBG_LO, Bglp + go);
            CPA16(sbb + FBU_HI, Buhp + go);
            CPA16(sbb + FBU_LO, Bulp + go);
            CPA_COMMIT();
        }
        uint32_t bo = (uint32_t)(it & 1) * F_BUF;
#pragma unroll
        for (int k0 = 0; k0 < 32; k0 += 16) {
            uint32_t ah[4][4], al[4][4], bh[4], bl[4];
            uint32_t brow = b_ld + bo + (uint32_t)k0 * 144u;
            ldsm4t(bh, brow + FBG_HI);
            ldsm4t(bl, brow + FBG_LO);
#pragma unroll
            for (int mt = 0; mt < 4; mt++) {
                uint32_t ad = a_ld + bo + (uint32_t)mt * 1280u + (uint32_t)k0 * 2u;
                ldsm4(ah[mt], ad);
            }
#pragma unroll
            for (int mt = 0; mt < 4; mt++)
#pragma unroll
                for (int nt = 0; nt < 2; nt++)
                    mma16816(accg[mt][nt], ah[mt], bh[nt * 2], bh[nt * 2 + 1]);
#pragma unroll
            for (int mt = 0; mt < 4; mt++)
#pragma unroll
                for (int nt = 0; nt < 2; nt++)
                    mma16816(accg[mt][nt], ah[mt], bl[nt * 2], bl[nt * 2 + 1]);
#pragma unroll
            for (int mt = 0; mt < 4; mt++) {
                uint32_t ad = a_ld + bo + (uint32_t)mt * 1280u + (uint32_t)k0 * 2u;
                ldsm4(al[mt], ad + FA_LO);
            }
#pragma unroll
            for (int mt = 0; mt < 4; mt++)
#pragma unroll
                for (int nt = 0; nt < 2; nt++)
                    mma16816(accg[mt][nt], al[mt], bh[nt * 2], bh[nt * 2 + 1]);
            ldsm4t(bh, brow + FBU_HI);
            ldsm4t(bl, brow + FBU_LO);
#pragma unroll
            for (int mt = 0; mt < 4; mt++)
#pragma unroll
                for (int nt = 0; nt < 2; nt++)
                    mma16816(accu[mt][nt], ah[mt], bh[nt * 2], bh[nt * 2 + 1]);
#pragma unroll
            for (int mt = 0; mt < 4; mt++)
#pragma unroll
                for (int nt = 0; nt < 2; nt++)
                    mma16816(accu[mt][nt], ah[mt], bl[nt * 2], bl[nt * 2 + 1]);
#pragma unroll
            for (int mt = 0; mt < 4; mt++)
#pragma unroll
                for (int nt = 0; nt < 2; nt++)
                    mma16816(accu[mt][nt], al[mt], bh[nt * 2], bh[nt * 2 + 1]);
        }
        if (it + 1 < NIT) {
            CPA_WAIT0();
            __syncthreads();
        }
    }

    int g = lane >> 2, tg = lane & 3;
#pragma unroll
    for (int mt = 0; mt < 4; mt++) {
#pragma unroll
        for (int nt = 0; nt < 2; nt++) {
            int row0 = bm + wm * 64 + mt * 16 + g;
            int col = bn + wn * 16 + nt * 8 + tg * 2;
            float* dg = accg[mt][nt];
            float* du = accu[mt][nt];
            size_t o0 = (size_t)z * sC + (size_t)row0 * N + col;
            size_t o1 = o0 + (size_t)8 * N;
            float a0 = dg[0] / (1.f + expf(-dg[0])) * du[0];
            float a1 = dg[1] / (1.f + expf(-dg[1])) * du[1];
            float a2 = dg[2] / (1.f + expf(-dg[2])) * du[2];
            float a3 = dg[3] / (1.f + expf(-dg[3])) * du[3];
            __nv_bfloat162 h0 = __floats2bfloat162_rn(a0, a1);
            __nv_bfloat162 h1 = __floats2bfloat162_rn(a2, a3);
            __nv_bfloat162 l0 = __floats2bfloat162_rn(a0 - __bfloat162float(h0.x),
                                                      a1 - __bfloat162float(h0.y));
            __nv_bfloat162 l1 = __floats2bfloat162_rn(a2 - __bfloat162float(h1.x),
                                                      a3 - __bfloat162float(h1.y));
            *(__nv_bfloat162*)(acth + o0) = h0;
            *(__nv_bfloat162*)(acth + o1) = h1;
            *(__nv_bfloat162*)(actl + o0) = l0;
            *(__nv_bfloat162*)(actl + o1) = l1;
        }
    }
}

// Down-proj GEMM with split-K. z = expert * NSPLIT + slice.
template <int EPI>
__global__ void __launch_bounds__(256, 2) hgemm_k(
    const bf* __restrict__ Ah, const bf* __restrict__ Al,
    const bf* __restrict__ Bh, const bf* __restrict__ Bl,
    float* __restrict__ outC,
    int Kfull, int N, size_t sA, size_t sB,
    const int* __restrict__ disp, const float* __restrict__ wv)
{
    extern __shared__ char smem[];
    uint32_t sbu = smem_u32(smem);
    int tid = threadIdx.x, wid = tid >> 5, lane = tid & 31;
    int zexp = blockIdx.z / NSPLIT, zs = blockIdx.z % NSPLIT;
    int Ksl = Kfull / NSPLIT;
    int koff = zs * Ksl;
    int bm = blockIdx.y * 128, bn = blockIdx.x * 128;
    int wm = wid & 1, wn = wid >> 1;

    int arw = tid >> 1, ahalf = tid & 1;
    int bkr = tid >> 3, bseg = tid & 7;
    const bf* Ahp = Ah + (size_t)zexp * sA + (size_t)(bm + arw) * Kfull + koff + ahalf * 16;
    const bf* Alp = Al + (size_t)zexp * sA + (size_t)(bm + arw) * Kfull + koff + ahalf * 16;
    const bf* Bhp = Bh + (size_t)zexp * sB + (size_t)(koff + bkr) * N + bn + bseg * 16;
    const bf* Blp = Bl + (size_t)zexp * sB + (size_t)(koff + bkr) * N + bn + bseg * 16;
    uint32_t a_st = (uint32_t)arw * 80u + (uint32_t)ahalf * 32u;
    uint32_t b_st = B_HI + (uint32_t)bkr * 272u + (uint32_t)bseg * 32u;

    int li = lane & 15, kh = (lane >> 4) << 3;
    uint32_t a_ld = sbu + (uint32_t)(wm * 64 + li) * 80u + (uint32_t)kh * 2u;
    uint32_t b_ld = sbu + B_HI + (uint32_t)li * 272u + (uint32_t)(wn * 32 + kh) * 2u;

    float acc[4][4][4];
#pragma unroll
    for (int i = 0; i < 4; i++)
#pragma unroll
        for (int j = 0; j < 4; j++)
#pragma unroll
            for (int c = 0; c < 4; c++) acc[i][j][c] = 0.f;

    const int NIT = Ksl / 32;
    {
        uint32_t sa = sbu + a_st, sbb = sbu + b_st;
        CPA16(sa, Ahp);            CPA16(sa + 16, Ahp + 8);
        CPA16(sa + A_LO, Alp);     CPA16(sa + A_LO + 16, Alp + 8);
        CPA16(sbb, Bhp);           CPA16(sbb + 16, Bhp + 8);
        CPA16(sbb + (B_LO - B_HI), Blp); CPA16(sbb + (B_LO - B_HI) + 16, Blp + 8);
        CPA_COMMIT();
        CPA_WAIT0();
    }
    __syncthreads();

    for (int it = 0; it < NIT; it++) {
        if (it + 1 < NIT) {
            int k0 = (it + 1) * 32;
            uint32_t so = (uint32_t)((it + 1) & 1) * SM_BUF;
            uint32_t sa = sbu + so + a_st, sbb = sbu + so + b_st;
            const bf* ah = Ahp + k0;
            const bf* al = Alp + k0;
            const bf* bh = Bhp + (size_t)k0 * N;
            const bf* bl = Blp + (size_t)k0 * N;
            CPA16(sa, ah);            CPA16(sa + 16, ah + 8);
            CPA16(sa + A_LO, al);     CPA16(sa + A_LO + 16, al + 8);
            CPA16(sbb, bh);           CPA16(sbb + 16, bh + 8);
            CPA16(sbb + (B_LO - B_HI), bl); CPA16(sbb + (B_LO - B_HI) + 16, bl + 8);
            CPA_COMMIT();
        }
        uint32_t bo = (uint32_t)(it & 1) * SM_BUF;
#pragma unroll
        for (int k0 = 0; k0 < 32; k0 += 16) {
            uint32_t ah[4][4], al[4][4], bh[4], bl[4];
            uint32_t bd0 = b_ld + bo + (uint32_t)k0 * 272u;
            ldsm4t(bh, bd0);
            ldsm4t(bl, bd0 + (B_LO - B_HI));
#pragma unroll
            for (int mt = 0; mt < 4; mt++) {
                uint32_t ad = a_ld + bo + (uint32_t)mt * 1280u + (uint32_t)k0 * 2u;
                ldsm4(ah[mt], ad);
            }
#pragma unroll
            for (int mt = 0; mt < 4; mt++)
#pragma unroll
                for (int half = 0; half < 2; half++)
                    mma16816(acc[mt][half], ah[mt], bh[half * 2], bh[half * 2 + 1]);
#pragma unroll
            for (int mt = 0; mt < 4; mt++)
#pragma unroll
                for (int half = 0; half < 2; half++)
                    mma16816(acc[mt][half], ah[mt], bl[half * 2], bl[half * 2 + 1]);
#pragma unroll
            for (int mt = 0; mt < 4; mt++) {
                uint32_t ad = a_ld + bo + (uint32_t)mt * 1280u + (uint32_t)k0 * 2u;
                ldsm4(al[mt], ad + A_LO);
            }
#pragma unroll
            for (int mt = 0; mt < 4; mt++)
#pragma unroll
                for (int half = 0; half < 2; half++)
                    mma16816(acc[mt][half], al[mt], bh[half * 2], bh[half * 2 + 1]);
            uint32_t bd1 = bd0 + 32u;
            ldsm4t(bh, bd1);
            ldsm4t(bl, bd1 + (B_LO - B_HI));
#pragma unroll
            for (int mt = 0; mt < 4; mt++)
#pragma unroll
                for (int half = 0; half < 2; half++)
                    mma16816(acc[mt][2 + half], ah[mt], bh[half * 2], bh[half * 2 + 1]);
#pragma unroll
            for (int mt = 0; mt < 4; mt++)
#pragma unroll
                for (int half = 0; half < 2; half++)
                    mma16816(acc[mt][2 + half], ah[mt], bl[half * 2], bl[half * 2 + 1]);
#pragma unroll
            for (int mt = 0; mt < 4; mt++)
#pragma unroll
                for (int half = 0; half < 2; half++)
                    mma16816(acc[mt][2 + half], al[mt], bh[half * 2], bh[half * 2 + 1]);
        }
        if (it + 1 < NIT) {
            CPA_WAIT0();
            __syncthreads();
        }
    }

    int g = lane >> 2, tg = lane & 3;
#pragma unroll
    for (int mt = 0; mt < 4; mt++) {
#pragma unroll
        for (int nt = 0; nt < 4; nt++) {
            int row0 = bm + wm * 64 + mt * 16 + g;
            int col = bn + wn * 32 + nt * 8 + tg * 2;
            float* d = acc[mt][nt];
            if (EPI == 0) {
                float* p0 = outC + (size_t)row0 * N + col;
                float* p1 = p0 + (size_t)8 * N;
                atomicAdd(p0 + 0, d[0]);
                atomicAdd(p0 + 1, d[1]);
                atomicAdd(p1 + 0, d[2]);
                atomicAdd(p1 + 1, d[3]);
            } else {
                int s0 = zexp * CAP + row0, s1 = s0 + 8;
                int t0 = disp[s0], t1 = disp[s1];
                float w0 = wv[s0], w1 = wv[s1];
                float* p0 = outC + (size_t)t0 * HH + col;
                float* p1 = outC + (size_t)t1 * HH + col;
                atomicAdd(p0 + 0, w0 * d[0]);
                atomicAdd(p0 + 1, w0 * d[1]);
                atomicAdd(p1 + 0, w1 * d[2]);
                atomicAdd(p1 + 1, w1 * d[3]);
            }
        }
    }
}

extern "C" void kernel_launch(void* const* d_in, const int* in_sizes, int n_in,
                              void* d_out, int out_size)
{
    const float* x  = (const float*)d_in[0];
    const float* rw = (const float*)d_in[1];
    const float* rg = (const float*)d_in[2];
    const float* ru = (const float*)d_in[3];
    const float* rd = (const float*)d_in[4];
    const float* sg = (const float*)d_in[5];
    const float* su = (const float*)d_in[6];
    const float* sd = (const float*)d_in[7];
    float* out = (float*)d_out;

    bf *xh, *xl, *sgh, *sgl, *suh, *sul, *sdh, *sdl, *rgh, *rgl, *ruh, *rul, *rdh, *rdl;
    bf *acth, *actl, *racth, *ractl;
    float *gw;
    int *disp;
    cudaGetSymbolAddress((void**)&xh, g_xh);   cudaGetSymbolAddress((void**)&xl, g_xl);
    cudaGetSymbolAddress((void**)&sgh, g_sgh); cudaGetSymbolAddress((void**)&sgl, g_sgl);
    cudaGetSymbolAddress((void**)&suh, g_suh); cudaGetSymbolAddress((void**)&sul, g_sul);
    cudaGetSymbolAddress((void**)&sdh, g_sdh); cudaGetSymbolAddress((void**)&sdl, g_sdl);
    cudaGetSymbolAddress((void**)&rgh, g_rgh); cudaGetSymbolAddress((void**)&rgl, g_rgl);
    cudaGetSymbolAddress((void**)&ruh, g_ruh); cudaGetSymbolAddress((void**)&rul, g_rul);
    cudaGetSymbolAddress((void**)&rdh, g_rdh); cudaGetSymbolAddress((void**)&rdl, g_rdl);
    cudaGetSymbolAddress((void**)&acth, g_acth); cudaGetSymbolAddress((void**)&actl, g_actl);
    cudaGetSymbolAddress((void**)&racth, g_racth); cudaGetSymbolAddress((void**)&ractl, g_ractl);
    cudaGetSymbolAddress((void**)&gw, g_gw);
    cudaGetSymbolAddress((void**)&disp, g_disp);

    cudaFuncSetAttribute(fused_gateup_k<false>, cudaFuncAttributeMaxDynamicSharedMemorySize, F_TOT);
    cudaFuncSetAttribute(fused_gateup_k<true>,  cudaFuncAttributeMaxDynamicSharedMemorySize, F_TOT);
    cudaFuncSetAttribute(hgemm_k<0>, cudaFuncAttributeMaxDynamicSharedMemorySize, SM_TOT);
    cudaFuncSetAttribute(hgemm_k<2>, cudaFuncAttributeMaxDynamicSharedMemorySize, SM_TOT);

    // side stream + events, created fresh per call (host-side only, leaked; few calls)
    cudaStream_t sB;
    cudaStreamCreateWithFlags(&sB, cudaStreamNonBlocking);
    cudaEvent_t ev0, evX, evM, evB;
    cudaEventCreateWithFlags(&ev0, cudaEventDisableTiming);
    cudaEventCreateWithFlags(&evX, cudaEventDisableTiming);
    cudaEventCreateWithFlags(&evM, cudaEventDisableTiming);
    cudaEventCreateWithFlags(&evB, cudaEventDisableTiming);

    // fork side stream from the capture (default) stream
    cudaEventRecord(ev0, 0);
    cudaStreamWaitEvent(sB, ev0, 0);

    // ---- default stream: shared-expert chain ----
    cvt_split<<<1184, 256>>>(x, xh, xl, (size_t)TT * HH);
    cudaEventRecord(evX, 0);
    cvt_split<<<1184, 256>>>(sg, sgh, sgl, (size_t)HH * ISS);
    cvt_split<<<1184, 256>>>(su, suh, sul, (size_t)HH * ISS);
    cvt_split<<<1184, 256>>>(sd, sdh, sdl, (size_t)ISS * HH);
    cudaMemsetAsync(out, 0, (size_t)TT * HH * sizeof(float), 0);
    cudaEventRecord(evM, 0);
    fused_gateup_k<false><<<dim3(ISS / 64, TT / 128, 1), 256, F_TOT>>>(
        xh, xl, sgh, sgl, suh, sul, acth, actl, HH, ISS, 0, 0, (const int*)0);
    hgemm_k<0><<<dim3(HH / 128, TT / 128, NSPLIT), 256, SM_TOT>>>(
        acth, actl, sdh, sdl, out, ISS, HH, 0, 0, (const int*)0, (const float*)0);

    // ---- side stream: routed chain ----
    cvt_split<<<1184, 256, 0, sB>>>(rg, rgh, rgl, (size_t)EE * HH * IRR);
    cvt_split<<<1184, 256, 0, sB>>>(ru, ruh, rul, (size_t)EE * HH * IRR);
    cvt_split<<<1184, 256, 0, sB>>>(rd, rdh, rdl, (size_t)EE * IRR * HH);
    router_kernel<<<TT, 256, 0, sB>>>(x, rw);
    dispatch_kernel<<<EE, 256, 0, sB>>>();
    cudaStreamWaitEvent(sB, evX, 0);   // needs xh/xl
    fused_gateup_k<true><<<dim3(IRR / 64, CAP / 128, EE), 256, F_TOT, sB>>>(
        xh, xl, rgh, rgl, ruh, rul, racth, ractl, HH, IRR,
        (size_t)HH * IRR, (size_t)CAP * IRR, disp);
    cudaStreamWaitEvent(sB, evM, 0);   // needs out zeroed
    hgemm_k<2><<<dim3(HH / 128, CAP / 128, EE * NSPLIT), 256, SM_TOT, sB>>>(
        racth, ractl, rdh, rdl, out, IRR, HH,
        (size_t)CAP * IRR, (size_t)IRR * HH, disp, gw);
    cudaEventRecord(evB, sB);

    // join back to the capture stream
    cudaStreamWaitEvent(0, evB, 0);
}